// round 10
// baseline (speedup 1.0000x reference)
#include <cuda_runtime.h>
#include <cstdint>

#define BB 2
#define NN 256
#define FF 64
#define HH 64
#define KK 50
#define CC 256
#define NT 512

// ---------------- device scratch ----------------
__device__ float g_A [BB*NN*KK];
__device__ float g_Bb[BB*NN*KK];
__device__ float g_U [BB*NN*HH];
__device__ float g_Wp[BB*NN*HH];

typedef unsigned long long ull;

// ---------------- helpers ----------------
__device__ __forceinline__ uint32_t smem_u32(const void* p) {
    uint32_t a;
    asm("{ .reg .u64 t; cvta.to.shared.u64 t, %1; cvt.u32.u64 %0, t; }" : "=r"(a) : "l"(p));
    return a;
}
__device__ __forceinline__ float siluf(float a) { return a * __fdividef(1.f, 1.f + __expf(-a)); }
__device__ __forceinline__ float sigm(float a)  { return __fdividef(1.f, 1.f + __expf(-a)); }
__device__ __forceinline__ float ftanh(float x) {
    float e = __expf(-2.f * fabsf(x));
    return copysignf(__fdividef(1.f - e, 1.f + e), x);
}
__device__ __forceinline__ void fma2(ull& acc, ull a, ull b) {
    asm("fma.rn.f32x2 %0, %1, %2, %0;" : "+l"(acc) : "l"(a), "l"(b));
}
__device__ __forceinline__ ull bcast2(float w) {
    ull r; asm("mov.b64 %0, {%1, %1};" : "=l"(r) : "f"(w)); return r;
}
__device__ __forceinline__ ull pack2(float a, float b) {
    ull r; asm("mov.b64 %0, {%1, %2};" : "=l"(r) : "f"(a), "f"(b)); return r;
}
__device__ __forceinline__ void unpack2(ull v, float& x, float& y) {
    asm("mov.b64 {%0, %1}, %2;" : "=f"(x), "=f"(y) : "l"(v));
}
__device__ __forceinline__ void cp16(uint32_t dst, const void* src) {
    asm volatile("cp.async.cg.shared.global [%0], [%1], 16;" :: "r"(dst), "l"(src) : "memory");
}
#define CP_COMMIT() asm volatile("cp.async.commit_group;" ::: "memory")
#define CP_WAIT0()  asm volatile("cp.async.wait_group 0;" ::: "memory")

// block reduce of 4 floats over 16 warps. red >= 68 floats, 16B aligned.
template<int DO_MAX>
__device__ __forceinline__ float4 block_red4(float4 v, int tid, float* red) {
    #pragma unroll
    for (int o = 16; o > 0; o >>= 1) {
        float ax = __shfl_xor_sync(~0u, v.x, o), ay = __shfl_xor_sync(~0u, v.y, o);
        float az = __shfl_xor_sync(~0u, v.z, o), aw = __shfl_xor_sync(~0u, v.w, o);
        if (DO_MAX) { v.x = fmaxf(v.x, ax); v.y = fmaxf(v.y, ay); v.z = fmaxf(v.z, az); v.w = fmaxf(v.w, aw); }
        else        { v.x += ax; v.y += ay; v.z += az; v.w += aw; }
    }
    if ((tid & 31) == 0) ((float4*)red)[tid >> 5] = v;
    __syncthreads();
    if (tid < 32) {
        float4 r;
        if (tid < 16) r = ((float4*)red)[tid];
        else { float id = DO_MAX ? __int_as_float(0xff800000) : 0.f; r = make_float4(id, id, id, id); }
        #pragma unroll
        for (int o = 8; o > 0; o >>= 1) {
            float ax = __shfl_xor_sync(~0u, r.x, o), ay = __shfl_xor_sync(~0u, r.y, o);
            float az = __shfl_xor_sync(~0u, r.z, o), aw = __shfl_xor_sync(~0u, r.w, o);
            if (DO_MAX) { r.x = fmaxf(r.x, ax); r.y = fmaxf(r.y, ay); r.z = fmaxf(r.z, az); r.w = fmaxf(r.w, aw); }
            else        { r.x += ax; r.y += ay; r.z += az; r.w += aw; }
        }
        if (tid == 0) ((float4*)red)[16] = r;
    }
    __syncthreads();
    float4 out = ((float4*)red)[16];
    __syncthreads();
    return out;
}

// ---------------- K0: per-node precompute ----------------
__global__ void prenode_kernel(const float* __restrict__ h,
                               const float* __restrict__ W_in,
                               const float* __restrict__ W_o1) {
    __shared__ float hs[FF];
    int node = blockIdx.x, t = threadIdx.x;
    if (t < FF) hs[t] = h[node * FF + t];
    __syncthreads();
    if (t < KK) {
        float a = 0.f, bv = 0.f;
        #pragma unroll
        for (int f = 0; f < FF; f++) { float hv = hs[f]; a += hv * W_in[f*KK+t]; bv += hv * W_in[(FF+f)*KK+t]; }
        g_A[node*KK+t] = a; g_Bb[node*KK+t] = bv;
    } else if (t >= 64 && t < 128) {
        int c = t - 64;
        float u = 0.f, w = 0.f;
        #pragma unroll
        for (int f = 0; f < FF; f++) { float hv = hs[f]; u += hv * W_o1[f*HH+c]; w += hv * W_o1[(FF+f)*HH+c]; }
        g_U[node*HH+c] = u; g_Wp[node*HH+c] = w;
    }
}

// ---------------- smem layout (float offsets) ----------------
#define O_HE     0        // he[256 j][65] = 16640
#define O_ATT    16640    // 1024
#define O_XDN    17664    // 1024
#define O_CMX    18688    // 256 (also phase-6 partial scratch)
#define O_CMY    18944
#define O_CMZ    19200
#define O_CN     19456    // 256 (alias en_s during phase 1)
#define O_P1     19712
#define O_HCOMB  19776
#define O_N1     19840
#define O_HN     19904
#define O_HESUM  19968    // 256
#define O_HEA    20224    // 512 (he_e half partials)
#define O_HI     20736
#define O_WIB    20800
#define O_WON    20864
#define O_BO2    20928
#define O_BI     20992
#define O_MEAN   21056
#define O_BETA   21120
#define O_WS     21184    // 256
#define O_BSG    21440    // 8
#define O_XI     21448    // 4
#define O_RED    21452    // 68 -> 21520 (byte 85808, 16B aligned)
#define O_UNION  21520
// phase-1 view of union:
#define O_SARR   21520    // 256*50 = 12800
#define O_WO1K   34320    // 3200
#define O_WO2    37520    // 4096 -> 41616
// phase-4 view of union:
#define O_HET    21520    // heT[256 c][84] = 21504 (4 groups of 16 j + 4-float holes)
#define O_WCH    43024    // 2 * 4096 = 8192 -> 51216 (byte 172096, 16B aligned)
// phase-6 view: cat[384] at O_HET
#define SMEM_FLOATS 51216
#define SMEM_BYTES  (SMEM_FLOATS*4)   // 204864

// ---------------- K1: fused per-(b,i) kernel, 512 threads ----------------
__global__ __launch_bounds__(NT, 1)
void sake_kernel(const float* __restrict__ h, const float* __restrict__ x,
                 const float* __restrict__ v,
                 const float* __restrict__ means, const float* __restrict__ betas,
                 const float* __restrict__ b_in,
                 const float* __restrict__ W_o1, const float* __restrict__ b_o1,
                 const float* __restrict__ W_o2, const float* __restrict__ b_o2,
                 const float* __restrict__ Ws,  const float* __restrict__ bs,
                 const float* __restrict__ log_gamma,
                 const float* __restrict__ Wx,
                 const float* __restrict__ Wp1, const float* __restrict__ bp1,
                 const float* __restrict__ Wp2, const float* __restrict__ bp2,
                 const float* __restrict__ Wn1, const float* __restrict__ bn1,
                 const float* __restrict__ Wn2, const float* __restrict__ bn2,
                 const float* __restrict__ Wv_mix,
                 const float* __restrict__ Wvel1, const float* __restrict__ bvel1,
                 const float* __restrict__ Wvel2,
                 float* __restrict__ outH, float* __restrict__ outX,
                 float* __restrict__ outV) {
    extern __shared__ float sm[];
    const int tid = threadIdx.x, wid = tid >> 5, lane = tid & 31;
    const int bid = blockIdx.x, b = bid >> 8, i = bid & 255, nodeI = bid;

    float* he    = sm + O_HE;     // [256 j][65]
    float* att_s = sm + O_ATT;
    float* xdn   = sm + O_XDN;
    float* en_s  = sm + O_CN;     // alias, phase-1 only
    float* he_e  = sm + O_HESUM;
    float* heA   = sm + O_HEA;
    float* hi_s  = sm + O_HI;
    float* wib   = sm + O_WIB;
    float* won   = sm + O_WON;
    float* bo2_s = sm + O_BO2;
    float* bi_s  = sm + O_BI;
    float* mn_s  = sm + O_MEAN;
    float* bt_s  = sm + O_BETA;
    float* ws_s  = sm + O_WS;
    float* bsg   = sm + O_BSG;
    float* xi_s  = sm + O_XI;
    float* red   = sm + O_RED;
    float* sarr  = sm + O_SARR;
    float* wo1k  = sm + O_WO1K;
    float* wo2   = sm + O_WO2;
    float* heT   = sm + O_HET;    // [256 c][84]

    const uint32_t smb = smem_u32(sm);

    // ---- preload ----
    if (tid < FF) {
        hi_s[tid]  = h[nodeI*FF+tid];
        wib[tid]   = g_Wp[nodeI*HH+tid] + b_o1[tid];
        won[tid]   = W_o1[178*HH+tid];
        bo2_s[tid] = b_o2[tid];
    }
    if (tid < KK) {
        bi_s[tid] = g_Bb[nodeI*KK+tid] + b_in[tid];
        mn_s[tid] = means[tid];
        bt_s[tid] = betas[tid];
    }
    if (tid < 256) ws_s[tid] = Ws[tid];
    if (tid < 4) {
        bsg[tid]   = bs[tid];
        bsg[4+tid] = __expf(log_gamma[tid]);
        if (tid < 3) xi_s[tid] = x[nodeI*3+tid];
    }
    for (int idx = tid; idx < NN*HH; idx += NT) {
        int j2 = idx >> 6, f = idx & 63;
        he[j2*65+f] = g_U[b*NN*HH + idx];
    }
    for (int idx = tid; idx < KK*HH; idx += NT) wo1k[idx] = W_o1[128*HH + idx];
    for (int idx = tid; idx < HH*HH; idx += NT) wo2[idx]  = W_o2[idx];
    __syncthreads();

    // ---- phase 0: geometry (thread pair (j, half)) ----
    const int j = tid >> 1, half = tid & 1, fb = half*32;
    float xjx = x[(b*NN+j)*3+0], xjy = x[(b*NN+j)*3+1], xjz = x[(b*NN+j)*3+2];
    float dx = xjx - xi_s[0], dy = xjy - xi_s[1], dz = xjz - xi_s[2];
    float d2 = fmaxf(dx*dx + dy*dy + dz*dz, 0.f);
    float normv = sqrtf(d2 + 1e-5f);
    float rinv  = __fdividef(1.f, normv + 1e-5f);
    if (half == 0) {
        *(float4*)&xdn[j*4] = make_float4(dx*rinv, dy*rinv, dz*rinv, normv);
        en_s[j] = __expf(-normv);
    }
    __syncthreads();

    // sarr[j][k] = rbf * hk (coalesced)
    for (int idx = tid; idx < NN*KK; idx += NT) {
        int j2 = idx / KK, k = idx - j2*KK;
        float aval = g_A[b*NN*KK + idx] + bi_s[k];
        float df = en_s[j2] - mn_s[k];
        sarr[idx] = __expf(-bt_s[k]*df*df) * aval;
    }
    __syncthreads();

    // ---- phase 1: edge model, pair-split over f ----
    {
        float accf[32];
        #pragma unroll
        for (int f = 0; f < 32; f++) accf[f] = he[j*65+fb+f] + wib[fb+f] + normv*won[fb+f];
        ull acc2[16];
        #pragma unroll
        for (int q = 0; q < 16; q++) acc2[q] = pack2(accf[2*q], accf[2*q+1]);

        #pragma unroll 2
        for (int k = 0; k < KK; k++) {
            ull s2 = bcast2(sarr[j*KK + k]);
            const ulonglong2* wr = (const ulonglong2*)&wo1k[k*64 + fb];
            #pragma unroll
            for (int q4 = 0; q4 < 8; q4++) {
                ulonglong2 wv = wr[q4];
                fma2(acc2[2*q4],   wv.x, s2);
                fma2(acc2[2*q4+1], wv.y, s2);
            }
        }
        #pragma unroll
        for (int q = 0; q < 16; q++) {
            float a0, a1; unpack2(acc2[q], a0, a1);
            he[j*65+fb+2*q]   = siluf(a0);
            he[j*65+fb+2*q+1] = siluf(a1);
        }
        __syncwarp();   // pair is in-warp: silu halves visible

        ull o2[16];
        const ulonglong2* bo = (const ulonglong2*)&bo2_s[fb];
        #pragma unroll
        for (int q = 0; q < 8; q++) { ulonglong2 bv = bo[q]; o2[2*q] = bv.x; o2[2*q+1] = bv.y; }
        #pragma unroll 8
        for (int fi = 0; fi < 64; fi++) {
            ull ab = bcast2(he[j*65+fi]);
            const ulonglong2* wr = (const ulonglong2*)&wo2[fi*64 + fb];
            #pragma unroll
            for (int q = 0; q < 8; q++) {
                ulonglong2 wv = wr[q];
                fma2(o2[2*q],   wv.x, ab);
                fma2(o2[2*q+1], wv.y, ab);
            }
        }
        __syncwarp();   // all reads of silu values done before overwrite
        #pragma unroll
        for (int q = 0; q < 16; q++) {
            float r0, r1; unpack2(o2[q], r0, r1);
            he[j*65+fb+2*q]   = r0;
            he[j*65+fb+2*q+1] = r1;
        }
    }
    __syncthreads();

    // ---- phase 2: attentions (pair combines via shfl) ----
    {
        float z0 = 0.f, z1 = 0.f, z2 = 0.f, z3 = 0.f;
        #pragma unroll 4
        for (int f = 0; f < 32; f++) {
            int ff = fb + ((f + (half << 4)) & 31);   // rotate to avoid pair bank clash
            float a = he[j*65+ff];
            z0 += a*ws_s[ff*4+0]; z1 += a*ws_s[ff*4+1];
            z2 += a*ws_s[ff*4+2]; z3 += a*ws_s[ff*4+3];
        }
        z0 += __shfl_xor_sync(~0u, z0, 1); z1 += __shfl_xor_sync(~0u, z1, 1);
        z2 += __shfl_xor_sync(~0u, z2, 1); z3 += __shfl_xor_sync(~0u, z3, 1);
        z0 += bsg[0]; z1 += bsg[1]; z2 += bsg[2]; z3 += bsg[3];
        z0 = (z0 > 0.f) ? z0 : 2.f*(__expf(0.5f*z0) - 1.f);
        z1 = (z1 > 0.f) ? z1 : 2.f*(__expf(0.5f*z1) - 1.f);
        z2 = (z2 > 0.f) ? z2 : 2.f*(__expf(0.5f*z2) - 1.f);
        z3 = (z3 > 0.f) ? z3 : 2.f*(__expf(0.5f*z3) - 1.f);
        float diag = (j == i) ? 1e5f : 0.f;
        float4 el = make_float4(-(normv+diag)*bsg[4], -(normv+diag)*bsg[5],
                                -(normv+diag)*bsg[6], -(normv+diag)*bsg[7]);
        float4 sl = make_float4(z0-diag, z1-diag, z2-diag, z3-diag);

        float4 m  = block_red4<1>(el, tid, red);   // duplicates safe for max
        float4 ee = make_float4(__expf(el.x-m.x), __expf(el.y-m.y), __expf(el.z-m.z), __expf(el.w-m.w));
        float4 eem = (half == 0) ? ee : make_float4(0,0,0,0);
        float4 s  = block_red4<0>(eem, tid, red);
        float4 eucl = make_float4(__fdividef(ee.x,s.x), __fdividef(ee.y,s.y),
                                  __fdividef(ee.z,s.z), __fdividef(ee.w,s.w));

        m  = block_red4<1>(sl, tid, red);
        ee = make_float4(__expf(sl.x-m.x), __expf(sl.y-m.y), __expf(sl.z-m.z), __expf(sl.w-m.w));
        eem = (half == 0) ? ee : make_float4(0,0,0,0);
        s  = block_red4<0>(eem, tid, red);
        float4 sem = make_float4(__fdividef(ee.x,s.x), __fdividef(ee.y,s.y),
                                 __fdividef(ee.z,s.z), __fdividef(ee.w,s.w));

        float4 q4 = make_float4(eucl.x*sem.x, eucl.y*sem.y, eucl.z*sem.z, eucl.w*sem.w);
        m  = block_red4<1>(q4, tid, red);
        ee = make_float4(__expf(q4.x-m.x), __expf(q4.y-m.y), __expf(q4.z-m.z), __expf(q4.w-m.w));
        eem = (half == 0) ? ee : make_float4(0,0,0,0);
        s  = block_red4<0>(eem, tid, red);
        if (half == 0) {
            att_s[j*4+0] = __fdividef(ee.x, s.x);
            att_s[j*4+1] = __fdividef(ee.y, s.y);
            att_s[j*4+2] = __fdividef(ee.z, s.z);
            att_s[j*4+3] = __fdividef(ee.w, s.w);
        }
    }
    __syncthreads();   // phase-1 union dead -> heT / Wx ring

    // ---- phase 4: coeff = tanh(he_att @ Wx), reduced over j (phase 3 folded in) ----
    // 16 warps = 16 disjoint n-slices of 16 n. lane = jp(0..3)*8 + nq(0..7).
    // Thread tile: 16 j (8 packed pairs) x 2 n. Pass = 64 j; 4 passes.
    // heT[c][84]: group g of 16 j at float offset g*20 (banks 0/20/8/28; stride 84 keeps 16B align).
    {
        const int jp = lane >> 3, nq = lane & 7;
        const int nb = wid*16 + nq*2;
        const int cme = tid & 255, jh = tid >> 8;
        const int fme = cme >> 2, hme = cme & 3;
        float cmx[2] = {0,0}, cmy[2] = {0,0}, cmz[2] = {0,0};
        float heE = 0.f;

        #define STAGE(chunk, buf) do { \
            uint32_t _dst = smb + (uint32_t)(O_WCH + (buf)*4096)*4u + (uint32_t)tid*16u; \
            const float* _src = Wx + (chunk)*4096 + tid*4; \
            cp16(_dst,          _src); \
            cp16(_dst + 8192u,  _src + 2048); \
            CP_COMMIT(); \
        } while(0)

        for (int pass = 0; pass < 4; pass++) {
            const int j0 = pass*64;
            __syncthreads();            // prev pass ring + heT fully consumed
            STAGE(0, 0);
            // fill half of heT row cme (32 j) + accumulate he_e partial
            #pragma unroll 8
            for (int jj = 0; jj < 32; jj += 2) {
                int jl = jh*32 + jj;
                int jn = j0 + jl;
                float v0 = he[jn*65 + fme]     * att_s[jn*4 + hme];
                float v1 = he[(jn+1)*65 + fme] * att_s[(jn+1)*4 + hme];
                heE += v0 + v1;
                int off = ((jl >> 4)*20) + (jl & 15);
                *(ull*)&heT[cme*84 + off] = pack2(v0, v1);
            }

            ull acc[2][8];
            #pragma unroll
            for (int n = 0; n < 2; n++)
                #pragma unroll
                for (int p = 0; p < 8; p++) acc[n][p] = 0ull;

            for (int t = 0; t < 16; t++) {
                CP_WAIT0();
                __syncthreads();        // buf t&1 + heT visible; compute(t-1) done
                if (t < 15) STAGE(t+1, (t+1)&1);

                const float* wb = sm + O_WCH + (t&1)*4096;
                const int cb = t*16;
                #pragma unroll 4
                for (int cc = 0; cc < 16; cc++) {
                    const float* ar = heT + (cb+cc)*84 + jp*20;
                    ulonglong2 a0 = *(const ulonglong2*)(ar);
                    ulonglong2 a1 = *(const ulonglong2*)(ar + 4);
                    ulonglong2 a2 = *(const ulonglong2*)(ar + 8);
                    ulonglong2 a3 = *(const ulonglong2*)(ar + 12);
                    float2 w2 = *(const float2*)&wb[cc*256 + nb];
                    ull b0 = bcast2(w2.x), b1 = bcast2(w2.y);
                    fma2(acc[0][0], a0.x, b0); fma2(acc[0][1], a0.y, b0);
                    fma2(acc[0][2], a1.x, b0); fma2(acc[0][3], a1.y, b0);
                    fma2(acc[0][4], a2.x, b0); fma2(acc[0][5], a2.y, b0);
                    fma2(acc[0][6], a3.x, b0); fma2(acc[0][7], a3.y, b0);
                    fma2(acc[1][0], a0.x, b1); fma2(acc[1][1], a0.y, b1);
                    fma2(acc[1][2], a1.x, b1); fma2(acc[1][3], a1.y, b1);
                    fma2(acc[1][4], a2.x, b1); fma2(acc[1][5], a2.y, b1);
                    fma2(acc[1][6], a3.x, b1); fma2(acc[1][7], a3.y, b1);
                }
            }

            // epilogue: tanh + xd-weighted accumulate
            #pragma unroll
            for (int p = 0; p < 8; p++) {
                float4 x0 = *(const float4*)&xdn[(j0 + jp*16 + 2*p)*4];
                float4 x1 = *(const float4*)&xdn[(j0 + jp*16 + 2*p + 1)*4];
                #pragma unroll
                for (int n = 0; n < 2; n++) {
                    float c0, c1; unpack2(acc[n][p], c0, c1);
                    float t0 = ftanh(c0), t1 = ftanh(c1);
                    cmx[n] += x0.x*t0 + x1.x*t1;
                    cmy[n] += x0.y*t0 + x1.y*t1;
                    cmz[n] += x0.z*t0 + x1.z*t1;
                }
            }
        }
        heA[jh*256 + cme] = heE;   // folded phase-3 partial

        // reduce over jp groups (lane bits 3,4); lanes jp==0 store n-exclusive
        #pragma unroll
        for (int n = 0; n < 2; n++) {
            #pragma unroll
            for (int o = 8; o <= 16; o <<= 1) {
                cmx[n] += __shfl_xor_sync(~0u, cmx[n], o);
                cmy[n] += __shfl_xor_sync(~0u, cmy[n], o);
                cmz[n] += __shfl_xor_sync(~0u, cmz[n], o);
            }
        }
        if (jp == 0) {
            #pragma unroll
            for (int n = 0; n < 2; n++) {
                sm[O_CMX + nb + n] = cmx[n];
                sm[O_CMY + nb + n] = cmy[n];
                sm[O_CMZ + nb + n] = cmz[n];
            }
        }
    }
    __syncthreads();

    // ---- phase 5: comb_sum / comb_norm / delta_v ----
    float* cn    = sm + O_CN;
    float* p1_s  = sm + O_P1;
    float* hcomb = sm + O_HCOMB;
    float* n1_s  = sm + O_N1;
    float* hn_s  = sm + O_HN;
    float* part  = sm + O_CMX;    // reuse after cm reads below
    float* cat   = sm + O_HET;    // reuse (heT dead): [384]
    const float invN = 1.f/256.f;
    float csx = 0.f, csy = 0.f, csz = 0.f, wv = 0.f;
    if (tid < 256) {
        csx = sm[O_CMX + tid]*invN;
        csy = sm[O_CMY + tid]*invN;
        csz = sm[O_CMZ + tid]*invN;
        cn[tid] = csx*csx + csy*csy + csz*csz;
        wv = Wv_mix[tid];
        float hev = heA[tid] + heA[256 + tid];
        he_e[tid] = hev;
        cat[64 + tid] = hev;
        if (tid < 64) cat[tid] = hi_s[tid];
    }
    float4 dv4 = block_red4<0>(make_float4(wv*csx, wv*csy, wv*csz, 0.f), tid, red);

    // ---- phase 6: tail MLPs, 4-way split over threads 0-255 ----
    const int g6 = tid >> 6, o6 = tid & 63;
    if (tid < 256) {   // p1: 256 -> 64
        float a = 0.f;
        const float* wp = Wp1 + g6*64*64 + o6;
        const float* cnp = cn + g6*64;
        #pragma unroll 4
        for (int c = 0; c < 64; c++) a += cnp[c] * wp[c*64];
        part[tid] = a;
    }
    __syncthreads();
    if (tid < 64) {
        float a = bp1[tid] + part[tid] + part[64+tid] + part[128+tid] + part[192+tid];
        p1_s[tid] = siluf(a);
    }
    __syncthreads();
    if (tid < 256) {   // p2: 64 -> 64
        float a = 0.f;
        const float* wp = Wp2 + g6*16*64 + o6;
        #pragma unroll
        for (int f = 0; f < 16; f++) a += p1_s[g6*16+f] * wp[f*64];
        part[tid] = a;
    }
    __syncthreads();
    if (tid < 64) {
        float a = bp2[tid] + part[tid] + part[64+tid] + part[128+tid] + part[192+tid];
        float hc = siluf(a);
        hcomb[tid] = hc;
        cat[320 + tid] = hc;
    }
    __syncthreads();
    if (tid < 256) {   // n1: 384 -> 64
        float a = 0.f;
        const float* wp = Wn1 + g6*96*64 + o6;
        const float* cp = cat + g6*96;
        #pragma unroll 4
        for (int r = 0; r < 96; r++) a += cp[r] * wp[r*64];
        part[tid] = a;
    }
    __syncthreads();
    if (tid < 64) {
        float a = bn1[tid] + part[tid] + part[64+tid] + part[128+tid] + part[192+tid];
        n1_s[tid] = siluf(a);
    }
    __syncthreads();
    if (tid < 256) {   // n2: 64 -> 64
        float a = 0.f;
        const float* wp = Wn2 + g6*16*64 + o6;
        #pragma unroll
        for (int f = 0; f < 16; f++) a += n1_s[g6*16+f] * wp[f*64];
        part[tid] = a;
    }
    __syncthreads();
    if (tid < 64) {
        float a = bn2[tid] + part[tid] + part[64+tid] + part[128+tid] + part[192+tid];
        float hv = hi_s[tid] + siluf(a);
        hn_s[tid] = hv;
        outH[nodeI*64+tid] = hv;
    }
    __syncthreads();
    if (tid < 256) {   // vel1: 64 -> 64
        float a = 0.f;
        const float* wp = Wvel1 + g6*16*64 + o6;
        #pragma unroll
        for (int f = 0; f < 16; f++) a += hn_s[g6*16+f] * wp[f*64];
        part[tid] = a;
    }
    __syncthreads();
    float vl = 0.f;
    if (tid < 64) {
        float a = bvel1[tid] + part[tid] + part[64+tid] + part[128+tid] + part[192+tid];
        vl = siluf(a) * Wvel2[tid];
    }
    float4 vs = block_red4<0>(make_float4(vl, 0.f, 0.f, 0.f), tid, red);
    if (tid == 0) {
        float scale = 2.f * sigm(vs.x);
        float dvv[3] = {dv4.x, dv4.y, dv4.z};
        #pragma unroll
        for (int t = 0; t < 3; t++) {
            float vn = dvv[t] + scale * v[nodeI*3+t];
            outV[nodeI*3+t] = vn;
            outX[nodeI*3+t] = x[nodeI*3+t] + vn;
        }
    }
}

// ---------------- launch ----------------
extern "C" void kernel_launch(void* const* d_in, const int* in_sizes, int n_in,
                              void* d_out, int out_size) {
    const float* h      = (const float*)d_in[0];
    const float* x      = (const float*)d_in[1];
    const float* v      = (const float*)d_in[2];
    const float* means  = (const float*)d_in[3];
    const float* betas  = (const float*)d_in[4];
    const float* W_in   = (const float*)d_in[5];
    const float* b_in   = (const float*)d_in[6];
    const float* W_o1   = (const float*)d_in[7];
    const float* b_o1   = (const float*)d_in[8];
    const float* W_o2   = (const float*)d_in[9];
    const float* b_o2   = (const float*)d_in[10];
    const float* Ws     = (const float*)d_in[11];
    const float* bs     = (const float*)d_in[12];
    const float* lgam   = (const float*)d_in[13];
    const float* Wx     = (const float*)d_in[14];
    const float* Wp1    = (const float*)d_in[15];
    const float* bp1    = (const float*)d_in[16];
    const float* Wp2    = (const float*)d_in[17];
    const float* bp2    = (const float*)d_in[18];
    const float* Wn1    = (const float*)d_in[19];
    const float* bn1    = (const float*)d_in[20];
    const float* Wn2    = (const float*)d_in[21];
    const float* bn2    = (const float*)d_in[22];
    const float* Wv_mix = (const float*)d_in[23];
    const float* Wvel1  = (const float*)d_in[24];
    const float* bvel1  = (const float*)d_in[25];
    const float* Wvel2  = (const float*)d_in[26];

    float* out  = (float*)d_out;
    float* outH = out;
    float* outX = out + BB*NN*FF;
    float* outV = outX + BB*NN*3;

    cudaFuncSetAttribute(sake_kernel, cudaFuncAttributeMaxDynamicSharedMemorySize, SMEM_BYTES);

    prenode_kernel<<<BB*NN, 128>>>(h, W_in, W_o1);
    sake_kernel<<<BB*NN, NT, SMEM_BYTES>>>(
        h, x, v, means, betas, b_in, W_o1, b_o1, W_o2, b_o2,
        Ws, bs, lgam, Wx, Wp1, bp1, Wp2, bp2,
        Wn1, bn1, Wn2, bn2, Wv_mix, Wvel1, bvel1, Wvel2,
        outH, outX, outV);
}

// round 11
// speedup vs baseline: 1.0028x; 1.0028x over previous
#include <cuda_runtime.h>
#include <cstdint>

#define BB 2
#define NN 256
#define FF 64
#define HH 64
#define KK 50
#define CC 256

// ---------------- device scratch ----------------
__device__ float g_A [BB*NN*KK];
__device__ float g_Bb[BB*NN*KK];
__device__ float g_U [BB*NN*HH];
__device__ float g_Wp[BB*NN*HH];
__device__ float g_WxT_t[CC*CC];   // tf32-rounded Wx^T: [n][c]

typedef unsigned long long ull;

// ---------------- helpers ----------------
__device__ __forceinline__ uint32_t smem_u32(const void* p) {
    uint32_t a;
    asm("{ .reg .u64 t; cvta.to.shared.u64 t, %1; cvt.u32.u64 %0, t; }" : "=r"(a) : "l"(p));
    return a;
}
__device__ __forceinline__ float siluf(float a) { return a * __fdividef(1.f, 1.f + __expf(-a)); }
__device__ __forceinline__ float sigm(float a)  { return __fdividef(1.f, 1.f + __expf(-a)); }
__device__ __forceinline__ float ftanh(float x) {
    float e = __expf(-2.f * fabsf(x));
    return copysignf(__fdividef(1.f - e, 1.f + e), x);
}
__device__ __forceinline__ float tf32r(float a) {
    uint32_t u;
    asm("cvt.rna.tf32.f32 %0, %1;" : "=r"(u) : "f"(a));
    return __uint_as_float(u);
}
__device__ __forceinline__ void mma8(float4& d, uint32_t a0, uint32_t a1, uint32_t a2, uint32_t a3,
                                     uint32_t b0, uint32_t b1) {
    asm volatile("mma.sync.aligned.m16n8k8.row.col.f32.tf32.tf32.f32 "
        "{%0,%1,%2,%3}, {%4,%5,%6,%7}, {%8,%9}, {%0,%1,%2,%3};"
        : "+f"(d.x), "+f"(d.y), "+f"(d.z), "+f"(d.w)
        : "r"(a0), "r"(a1), "r"(a2), "r"(a3), "r"(b0), "r"(b1));
}
__device__ __forceinline__ void fma2(ull& acc, ull a, ull b) {
    asm("fma.rn.f32x2 %0, %1, %2, %0;" : "+l"(acc) : "l"(a), "l"(b));
}
__device__ __forceinline__ ull bcast2(float w) {
    ull r; asm("mov.b64 %0, {%1, %1};" : "=l"(r) : "f"(w)); return r;
}
__device__ __forceinline__ ull pack2(float a, float b) {
    ull r; asm("mov.b64 %0, {%1, %2};" : "=l"(r) : "f"(a), "f"(b)); return r;
}
__device__ __forceinline__ void unpack2(ull v, float& x, float& y) {
    asm("mov.b64 {%0, %1}, %2;" : "=f"(x), "=f"(y) : "l"(v));
}
__device__ __forceinline__ void cp16(uint32_t dst, const void* src) {
    asm volatile("cp.async.cg.shared.global [%0], [%1], 16;" :: "r"(dst), "l"(src) : "memory");
}
#define CP_COMMIT() asm volatile("cp.async.commit_group;" ::: "memory")
#define CP_WAIT0()  asm volatile("cp.async.wait_group 0;" ::: "memory")

// block reduce of 4 floats (8 warps / 256 threads). red >= 36 floats, 16B aligned.
template<int DO_MAX>
__device__ __forceinline__ float4 block_red4(float4 v, int tid, float* red) {
    #pragma unroll
    for (int o = 16; o > 0; o >>= 1) {
        float ax = __shfl_xor_sync(~0u, v.x, o), ay = __shfl_xor_sync(~0u, v.y, o);
        float az = __shfl_xor_sync(~0u, v.z, o), aw = __shfl_xor_sync(~0u, v.w, o);
        if (DO_MAX) { v.x = fmaxf(v.x, ax); v.y = fmaxf(v.y, ay); v.z = fmaxf(v.z, az); v.w = fmaxf(v.w, aw); }
        else        { v.x += ax; v.y += ay; v.z += az; v.w += aw; }
    }
    if ((tid & 31) == 0) ((float4*)red)[tid >> 5] = v;
    __syncthreads();
    if (tid < 32) {
        float4 r;
        if (tid < 8) r = ((float4*)red)[tid];
        else { float id = DO_MAX ? __int_as_float(0xff800000) : 0.f; r = make_float4(id, id, id, id); }
        #pragma unroll
        for (int o = 4; o > 0; o >>= 1) {
            float ax = __shfl_xor_sync(~0u, r.x, o), ay = __shfl_xor_sync(~0u, r.y, o);
            float az = __shfl_xor_sync(~0u, r.z, o), aw = __shfl_xor_sync(~0u, r.w, o);
            if (DO_MAX) { r.x = fmaxf(r.x, ax); r.y = fmaxf(r.y, ay); r.z = fmaxf(r.z, az); r.w = fmaxf(r.w, aw); }
            else        { r.x += ax; r.y += ay; r.z += az; r.w += aw; }
        }
        if (tid == 0) ((float4*)red)[8] = r;
    }
    __syncthreads();
    float4 out = ((float4*)red)[8];
    __syncthreads();
    return out;
}

// ---------------- K0a: transpose + tf32-round Wx ----------------
__global__ void wxt_kernel(const float* __restrict__ Wx) {
    int n = blockIdx.x, c = threadIdx.x;
    g_WxT_t[n*CC + c] = tf32r(Wx[c*CC + n]);
}

// ---------------- K0b: per-node precompute ----------------
__global__ void prenode_kernel(const float* __restrict__ h,
                               const float* __restrict__ W_in,
                               const float* __restrict__ W_o1) {
    __shared__ float hs[FF];
    int node = blockIdx.x, t = threadIdx.x;
    if (t < FF) hs[t] = h[node * FF + t];
    __syncthreads();
    if (t < KK) {
        float a = 0.f, bv = 0.f;
        #pragma unroll
        for (int f = 0; f < FF; f++) { float hv = hs[f]; a += hv * W_in[f*KK+t]; bv += hv * W_in[(FF+f)*KK+t]; }
        g_A[node*KK+t] = a; g_Bb[node*KK+t] = bv;
    } else if (t >= 64 && t < 128) {
        int c = t - 64;
        float u = 0.f, w = 0.f;
        #pragma unroll
        for (int f = 0; f < FF; f++) { float hv = hs[f]; u += hv * W_o1[f*HH+c]; w += hv * W_o1[(FF+f)*HH+c]; }
        g_U[node*HH+c] = u; g_Wp[node*HH+c] = w;
    }
}

// ---------------- smem layout (float offsets) ----------------
#define O_HE     0        // 256*65 = 16640
#define O_ATT    16640    // 1024
#define O_XDN    17664    // 1024
#define O_CMX    18688    // 256 (also phase-6 partial scratch)
#define O_CMY    18944
#define O_CMZ    19200
#define O_CN     19456
#define O_P1     19712
#define O_HCOMB  19776
#define O_N1     19840
#define O_HN     19904
#define O_HESUM  23808    // 256
#define O_HI     24064
#define O_WIB    24128
#define O_WON    24192
#define O_BO2    24256
#define O_BI     24320
#define O_MEAN   24384
#define O_BETA   24448
#define O_WS     24512    // 256
#define O_BSG    24768    // 8
#define O_XI     24776    // 4
#define O_RED    24784    // 36
#define O_UNION  24832
// phase-1 view of union:
#define O_AS     24832    // 256*51 = 13056
#define O_WO1K   37888    // 3200
#define O_WO2    41088    // 4096 -> 45184
// phase-4 view of union:
#define O_AHI    24832    // heA_hi[32 j][260] = 8320
#define O_ALO    33152    // heA_lo[32 j][260] = 8320
#define O_WCT    41472    // ring: 2 x [256 n][20] = 10240 -> 51712
// phase-6 view: cat[384] at O_AHI
#define SMEM_FLOATS 51712
#define SMEM_BYTES  (SMEM_FLOATS*4)   // 206848

// ---------------- K1: fused per-(b,i) kernel ----------------
__global__ __launch_bounds__(256, 1)
void sake_kernel(const float* __restrict__ h, const float* __restrict__ x,
                 const float* __restrict__ v,
                 const float* __restrict__ means, const float* __restrict__ betas,
                 const float* __restrict__ b_in,
                 const float* __restrict__ W_o1, const float* __restrict__ b_o1,
                 const float* __restrict__ W_o2, const float* __restrict__ b_o2,
                 const float* __restrict__ Ws,  const float* __restrict__ bs,
                 const float* __restrict__ log_gamma,
                 const float* __restrict__ Wp1, const float* __restrict__ bp1,
                 const float* __restrict__ Wp2, const float* __restrict__ bp2,
                 const float* __restrict__ Wn1, const float* __restrict__ bn1,
                 const float* __restrict__ Wn2, const float* __restrict__ bn2,
                 const float* __restrict__ Wv_mix,
                 const float* __restrict__ Wvel1, const float* __restrict__ bvel1,
                 const float* __restrict__ Wvel2,
                 float* __restrict__ outH, float* __restrict__ outX,
                 float* __restrict__ outV) {
    extern __shared__ float sm[];
    const int tid = threadIdx.x, wid = tid >> 5, lane = tid & 31;
    const int bid = blockIdx.x, b = bid >> 8, i = bid & 255, nodeI = bid;

    float* he    = sm + O_HE;     // [256 j][65]
    float* att_s = sm + O_ATT;    // [256 j][4]
    float* xdn   = sm + O_XDN;    // [256 j][4]
    float* he_e  = sm + O_HESUM;
    float* hi_s  = sm + O_HI;
    float* wib   = sm + O_WIB;
    float* won   = sm + O_WON;
    float* bo2_s = sm + O_BO2;
    float* bi_s  = sm + O_BI;
    float* mn_s  = sm + O_MEAN;
    float* bt_s  = sm + O_BETA;
    float* ws_s  = sm + O_WS;
    float* bsg   = sm + O_BSG;
    float* xi_s  = sm + O_XI;
    float* red   = sm + O_RED;
    float* As    = sm + O_AS;
    float* wo1k  = sm + O_WO1K;
    float* wo2   = sm + O_WO2;

    const uint32_t smb = smem_u32(sm);

    // ---- preload ----
    if (tid < FF) {
        hi_s[tid]  = h[nodeI*FF+tid];
        wib[tid]   = g_Wp[nodeI*HH+tid] + b_o1[tid];
        won[tid]   = W_o1[178*HH+tid];
        bo2_s[tid] = b_o2[tid];
    }
    if (tid < KK) {
        bi_s[tid] = g_Bb[nodeI*KK+tid] + b_in[tid];
        mn_s[tid] = means[tid];
        bt_s[tid] = betas[tid];
    }
    ws_s[tid] = Ws[tid];
    if (tid < 4) {
        bsg[tid]   = bs[tid];
        bsg[4+tid] = __expf(log_gamma[tid]);
        if (tid < 3) xi_s[tid] = x[nodeI*3+tid];
    }
    for (int idx = tid; idx < NN*KK; idx += 256) {
        int j2 = idx / KK, k = idx - j2*KK;
        As[j2*51+k] = g_A[b*NN*KK + idx];
    }
    for (int idx = tid; idx < NN*HH; idx += 256) {
        int j2 = idx >> 6, f = idx & 63;
        he[j2*65+f] = g_U[b*NN*HH + idx];
    }
    for (int idx = tid; idx < KK*HH; idx += 256) wo1k[idx] = W_o1[128*HH + idx];
    for (int idx = tid; idx < HH*HH; idx += 256) wo2[idx]  = W_o2[idx];
    __syncthreads();

    // ---- phase 1: edge model (thread = j), f32x2 ----
    const int j = tid;
    float xjx = x[(b*NN+j)*3+0], xjy = x[(b*NN+j)*3+1], xjz = x[(b*NN+j)*3+2];
    float dx = xjx - xi_s[0], dy = xjy - xi_s[1], dz = xjz - xi_s[2];
    float d2 = fmaxf(dx*dx + dy*dy + dz*dz, 0.f);
    float normv = sqrtf(d2 + 1e-5f);
    float rinv  = __fdividef(1.f, normv + 1e-5f);
    *(float4*)&xdn[j*4] = make_float4(dx*rinv, dy*rinv, dz*rinv, normv);
    float en = __expf(-normv);

    {
        float accf[64];
        #pragma unroll
        for (int f = 0; f < 64; f++) accf[f] = he[j*65+f] + wib[f] + normv*won[f];
        ull acc2[32];
        #pragma unroll
        for (int f2 = 0; f2 < 32; f2++) acc2[f2] = pack2(accf[2*f2], accf[2*f2+1]);

        #pragma unroll 2
        for (int k = 0; k < KK; k++) {
            float hk = As[j*51+k] + bi_s[k];
            float df = en - mn_s[k];
            float s  = __expf(-bt_s[k]*df*df) * hk;
            ull s2 = bcast2(s);
            const ulonglong2* wr = (const ulonglong2*)&wo1k[k*64];
            #pragma unroll
            for (int f4 = 0; f4 < 16; f4++) {
                ulonglong2 wv = wr[f4];
                fma2(acc2[2*f4],   wv.x, s2);
                fma2(acc2[2*f4+1], wv.y, s2);
            }
        }
        #pragma unroll
        for (int f2 = 0; f2 < 32; f2++) {
            float a0, a1; unpack2(acc2[f2], a0, a1);
            accf[2*f2] = siluf(a0); accf[2*f2+1] = siluf(a1);
        }

        #pragma unroll
        for (int g = 0; g < 4; g++) {
            ull o2[8];
            const ulonglong2* bo = (const ulonglong2*)&bo2_s[g*16];
            #pragma unroll
            for (int q = 0; q < 4; q++) { ulonglong2 bv = bo[q]; o2[2*q] = bv.x; o2[2*q+1] = bv.y; }
            #pragma unroll 8
            for (int f = 0; f < 64; f++) {
                ull ab = bcast2(accf[f]);
                const ulonglong2* wr = (const ulonglong2*)&wo2[f*64 + g*16];
                #pragma unroll
                for (int q = 0; q < 4; q++) {
                    ulonglong2 wv = wr[q];
                    fma2(o2[2*q],   wv.x, ab);
                    fma2(o2[2*q+1], wv.y, ab);
                }
            }
            #pragma unroll
            for (int q = 0; q < 8; q++) {
                float r0, r1; unpack2(o2[q], r0, r1);
                he[j*65 + g*16 + 2*q]     = r0;
                he[j*65 + g*16 + 2*q + 1] = r1;
            }
        }
    }

    // ---- phase 2: attentions (softmax over j) ----
    float z0 = bsg[0], z1 = bsg[1], z2 = bsg[2], z3 = bsg[3];
    for (int f = 0; f < 64; f++) {
        float a = he[j*65+f];
        z0 += a*ws_s[f*4+0]; z1 += a*ws_s[f*4+1]; z2 += a*ws_s[f*4+2]; z3 += a*ws_s[f*4+3];
    }
    z0 = (z0 > 0.f) ? z0 : 2.f*(__expf(0.5f*z0) - 1.f);
    z1 = (z1 > 0.f) ? z1 : 2.f*(__expf(0.5f*z1) - 1.f);
    z2 = (z2 > 0.f) ? z2 : 2.f*(__expf(0.5f*z2) - 1.f);
    z3 = (z3 > 0.f) ? z3 : 2.f*(__expf(0.5f*z3) - 1.f);
    float diag = (j == i) ? 1e5f : 0.f;
    float4 el = make_float4(-(normv+diag)*bsg[4], -(normv+diag)*bsg[5],
                            -(normv+diag)*bsg[6], -(normv+diag)*bsg[7]);
    float4 sl = make_float4(z0-diag, z1-diag, z2-diag, z3-diag);

    float4 m  = block_red4<1>(el, tid, red);
    float4 ee = make_float4(__expf(el.x-m.x), __expf(el.y-m.y), __expf(el.z-m.z), __expf(el.w-m.w));
    float4 s  = block_red4<0>(ee, tid, red);
    float4 eucl = make_float4(__fdividef(ee.x,s.x), __fdividef(ee.y,s.y),
                              __fdividef(ee.z,s.z), __fdividef(ee.w,s.w));
    m  = block_red4<1>(sl, tid, red);
    ee = make_float4(__expf(sl.x-m.x), __expf(sl.y-m.y), __expf(sl.z-m.z), __expf(sl.w-m.w));
    s  = block_red4<0>(ee, tid, red);
    float4 sem = make_float4(__fdividef(ee.x,s.x), __fdividef(ee.y,s.y),
                             __fdividef(ee.z,s.z), __fdividef(ee.w,s.w));
    float4 q4 = make_float4(eucl.x*sem.x, eucl.y*sem.y, eucl.z*sem.z, eucl.w*sem.w);
    m  = block_red4<1>(q4, tid, red);
    ee = make_float4(__expf(q4.x-m.x), __expf(q4.y-m.y), __expf(q4.z-m.z), __expf(q4.w-m.w));
    s  = block_red4<0>(ee, tid, red);
    att_s[j*4+0] = __fdividef(ee.x, s.x);
    att_s[j*4+1] = __fdividef(ee.y, s.y);
    att_s[j*4+2] = __fdividef(ee.z, s.z);
    att_s[j*4+3] = __fdividef(ee.w, s.w);
    __syncthreads();   // phase-1 union dead -> heA / WxT ring

    // ---- phase 4: coeff = tanh(he_att @ Wx) via tf32 mma.sync (2-term A split) ----
    // 8 warps = 2 jg x 4 ng. Warp tile per pass: 16 j x 64 n (8 mma n-tiles).
    // Pass = 32 j; 8 passes. K chunk = 16 c, ring of 2. Phase 3 (he_e) folded into fill.
    {
        const int jg = wid >> 2, ng = wid & 3;
        const int grp = lane >> 2, tig = lane & 3;
        const int fme = tid >> 2, hme = tid & 3;
        float* heAh = sm + O_AHI;
        float* heAl = sm + O_ALO;
        float cmx[16], cmy[16], cmz[16];
        #pragma unroll
        for (int q = 0; q < 16; q++) { cmx[q] = 0.f; cmy[q] = 0.f; cmz[q] = 0.f; }
        float heE = 0.f;

        #define STG(chunk, buf) do { \
            uint32_t _dst = smb + (uint32_t)(O_WCT + (buf)*5120)*4u + (uint32_t)tid*80u; \
            const float* _src = g_WxT_t + tid*256 + (chunk)*16; \
            cp16(_dst,       _src); \
            cp16(_dst + 16u, _src + 4); \
            cp16(_dst + 32u, _src + 8); \
            cp16(_dst + 48u, _src + 12); \
            CP_COMMIT(); \
        } while(0)

        for (int pass = 0; pass < 8; pass++) {
            const int j0 = pass*32;
            __syncthreads();            // prev pass ring + heA fully consumed
            STG(0, 0);
            // fill heA_hi/lo[jj][c=tid] + he_e partial (fp32 exact)
            #pragma unroll 4
            for (int jj = 0; jj < 32; jj++) {
                int jn = j0 + jj;
                float val = he[jn*65 + fme] * att_s[jn*4 + hme];
                heE += val;
                float hi = tf32r(val);
                heAh[jj*260 + tid] = hi;
                heAl[jj*260 + tid] = tf32r(val - hi);
            }

            float4 acc[8];
            #pragma unroll
            for (int s4 = 0; s4 < 8; s4++) acc[s4] = make_float4(0.f, 0.f, 0.f, 0.f);

            for (int t = 0; t < 16; t++) {
                CP_WAIT0();
                __syncthreads();        // buf t&1 + heA visible; compute(t-1) done
                if (t < 15) STG(t+1, (t+1)&1);

                const float* wb = sm + O_WCT + (t&1)*5120;
                #pragma unroll
                for (int ks = 0; ks < 2; ks++) {
                    const int kl = ks*8;
                    const float* ab = heAh + (jg*16 + grp)*260 + t*16 + kl + tig;
                    uint32_t ah0 = __float_as_uint(ab[0]);
                    uint32_t ah1 = __float_as_uint(ab[8*260]);
                    uint32_t ah2 = __float_as_uint(ab[4]);
                    uint32_t ah3 = __float_as_uint(ab[8*260+4]);
                    const float* al = heAl + (jg*16 + grp)*260 + t*16 + kl + tig;
                    uint32_t al0 = __float_as_uint(al[0]);
                    uint32_t al1 = __float_as_uint(al[8*260]);
                    uint32_t al2 = __float_as_uint(al[4]);
                    uint32_t al3 = __float_as_uint(al[8*260+4]);
                    #pragma unroll
                    for (int s4 = 0; s4 < 8; s4++) {
                        const float* bb = wb + (ng*64 + s4*8 + grp)*20 + kl + tig;
                        uint32_t b0 = __float_as_uint(bb[0]);
                        uint32_t b1 = __float_as_uint(bb[4]);
                        mma8(acc[s4], ah0, ah1, ah2, ah3, b0, b1);
                        mma8(acc[s4], al0, al1, al2, al3, b0, b1);
                    }
                }
            }

            // epilogue: tanh + xd-weighted j-accumulate
            float4 xd0 = *(const float4*)&xdn[(j0 + jg*16 + grp)*4];
            float4 xd1 = *(const float4*)&xdn[(j0 + jg*16 + grp + 8)*4];
            #pragma unroll
            for (int s4 = 0; s4 < 8; s4++) {
                float t0 = ftanh(acc[s4].x), t1 = ftanh(acc[s4].y);
                float t2 = ftanh(acc[s4].z), t3 = ftanh(acc[s4].w);
                cmx[2*s4]   += xd0.x*t0 + xd1.x*t2;
                cmy[2*s4]   += xd0.y*t0 + xd1.y*t2;
                cmz[2*s4]   += xd0.z*t0 + xd1.z*t2;
                cmx[2*s4+1] += xd0.x*t1 + xd1.x*t3;
                cmy[2*s4+1] += xd0.y*t1 + xd1.y*t3;
                cmz[2*s4+1] += xd0.z*t1 + xd1.z*t3;
            }
        }
        he_e[tid] = heE;   // folded phase 3

        // reduce over grp (lanes with same tig): shfl offsets 4, 8, 16
        #pragma unroll
        for (int q = 0; q < 16; q++) {
            #pragma unroll
            for (int o = 4; o <= 16; o <<= 1) {
                cmx[q] += __shfl_xor_sync(~0u, cmx[q], o);
                cmy[q] += __shfl_xor_sync(~0u, cmy[q], o);
                cmz[q] += __shfl_xor_sync(~0u, cmz[q], o);
            }
        }
        // jg=0 writes, then jg=1 adds (distinct n per (ng, lane, s))
        if (jg == 0 && lane < 4) {
            #pragma unroll
            for (int s4 = 0; s4 < 8; s4++) {
                int n0 = ng*64 + s4*8 + 2*lane;
                sm[O_CMX + n0]     = cmx[2*s4];
                sm[O_CMX + n0 + 1] = cmx[2*s4+1];
                sm[O_CMY + n0]     = cmy[2*s4];
                sm[O_CMY + n0 + 1] = cmy[2*s4+1];
                sm[O_CMZ + n0]     = cmz[2*s4];
                sm[O_CMZ + n0 + 1] = cmz[2*s4+1];
            }
        }
        __syncthreads();
        if (jg == 1 && lane < 4) {
            #pragma unroll
            for (int s4 = 0; s4 < 8; s4++) {
                int n0 = ng*64 + s4*8 + 2*lane;
                sm[O_CMX + n0]     += cmx[2*s4];
                sm[O_CMX + n0 + 1] += cmx[2*s4+1];
                sm[O_CMY + n0]     += cmy[2*s4];
                sm[O_CMY + n0 + 1] += cmy[2*s4+1];
                sm[O_CMZ + n0]     += cmz[2*s4];
                sm[O_CMZ + n0 + 1] += cmz[2*s4+1];
            }
        }
    }
    __syncthreads();

    // ---- phase 5: comb_sum / comb_norm / delta_v ----
    float* cn    = sm + O_CN;
    float* p1_s  = sm + O_P1;
    float* hcomb = sm + O_HCOMB;
    float* n1_s  = sm + O_N1;
    float* hn_s  = sm + O_HN;
    float* part  = sm + O_CMX;    // reuse after cm reads below
    float* cat   = sm + O_AHI;    // reuse (heA dead): [384]
    const float invN = 1.f/256.f;
    float csx = sm[O_CMX + tid]*invN, csy = sm[O_CMY + tid]*invN, csz = sm[O_CMZ + tid]*invN;
    cn[tid] = csx*csx + csy*csy + csz*csz;
    float wv = Wv_mix[tid];
    float4 dv4 = block_red4<0>(make_float4(wv*csx, wv*csy, wv*csz, 0.f), tid, red);
    cat[64 + tid] = he_e[tid];
    if (tid < 64) cat[tid] = hi_s[tid];

    // ---- phase 6: tail MLPs, 4-way split over 256 threads ----
    const int g6 = tid >> 6, o6 = tid & 63;
    {   // p1: 256 -> 64
        float a = 0.f;
        const float* wp = Wp1 + g6*64*64 + o6;
        const float* cnp = cn + g6*64;
        #pragma unroll 4
        for (int c = 0; c < 64; c++) a += cnp[c] * wp[c*64];
        part[tid] = a;
    }
    __syncthreads();
    if (tid < 64) {
        float a = bp1[tid] + part[tid] + part[64+tid] + part[128+tid] + part[192+tid];
        p1_s[tid] = siluf(a);
    }
    __syncthreads();
    {   // p2: 64 -> 64
        float a = 0.f;
        const float* wp = Wp2 + g6*16*64 + o6;
        #pragma unroll
        for (int f = 0; f < 16; f++) a += p1_s[g6*16+f] * wp[f*64];
        part[tid] = a;
    }
    __syncthreads();
    if (tid < 64) {
        float a = bp2[tid] + part[tid] + part[64+tid] + part[128+tid] + part[192+tid];
        float hc = siluf(a);
        hcomb[tid] = hc;
        cat[320 + tid] = hc;
    }
    __syncthreads();
    {   // n1: 384 -> 64
        float a = 0.f;
        const float* wp = Wn1 + g6*96*64 + o6;
        const float* cp = cat + g6*96;
        #pragma unroll 4
        for (int r = 0; r < 96; r++) a += cp[r] * wp[r*64];
        part[tid] = a;
    }
    __syncthreads();
    if (tid < 64) {
        float a = bn1[tid] + part[tid] + part[64+tid] + part[128+tid] + part[192+tid];
        n1_s[tid] = siluf(a);
    }
    __syncthreads();
    {   // n2: 64 -> 64
        float a = 0.f;
        const float* wp = Wn2 + g6*16*64 + o6;
        #pragma unroll
        for (int f = 0; f < 16; f++) a += n1_s[g6*16+f] * wp[f*64];
        part[tid] = a;
    }
    __syncthreads();
    if (tid < 64) {
        float a = bn2[tid] + part[tid] + part[64+tid] + part[128+tid] + part[192+tid];
        float hv = hi_s[tid] + siluf(a);
        hn_s[tid] = hv;
        outH[nodeI*64+tid] = hv;
    }
    __syncthreads();
    {   // vel1: 64 -> 64
        float a = 0.f;
        const float* wp = Wvel1 + g6*16*64 + o6;
        #pragma unroll
        for (int f = 0; f < 16; f++) a += hn_s[g6*16+f] * wp[f*64];
        part[tid] = a;
    }
    __syncthreads();
    float vl = 0.f;
    if (tid < 64) {
        float a = bvel1[tid] + part[tid] + part[64+tid] + part[128+tid] + part[192+tid];
        vl = siluf(a) * Wvel2[tid];
    }
    float4 vs = block_red4<0>(make_float4(vl, 0.f, 0.f, 0.f), tid, red);
    if (tid == 0) {
        float scale = 2.f * sigm(vs.x);
        float dvv[3] = {dv4.x, dv4.y, dv4.z};
        #pragma unroll
        for (int t = 0; t < 3; t++) {
            float vn = dvv[t] + scale * v[nodeI*3+t];
            outV[nodeI*3+t] = vn;
            outX[nodeI*3+t] = x[nodeI*3+t] + vn;
        }
    }
}

// ---------------- launch ----------------
extern "C" void kernel_launch(void* const* d_in, const int* in_sizes, int n_in,
                              void* d_out, int out_size) {
    const float* h      = (const float*)d_in[0];
    const float* x      = (const float*)d_in[1];
    const float* v      = (const float*)d_in[2];
    const float* means  = (const float*)d_in[3];
    const float* betas  = (const float*)d_in[4];
    const float* W_in   = (const float*)d_in[5];
    const float* b_in   = (const float*)d_in[6];
    const float* W_o1   = (const float*)d_in[7];
    const float* b_o1   = (const float*)d_in[8];
    const float* W_o2   = (const float*)d_in[9];
    const float* b_o2   = (const float*)d_in[10];
    const float* Ws     = (const float*)d_in[11];
    const float* bs     = (const float*)d_in[12];
    const float* lgam   = (const float*)d_in[13];
    const float* Wx     = (const float*)d_in[14];
    const float* Wp1    = (const float*)d_in[15];
    const float* bp1    = (const float*)d_in[16];
    const float* Wp2    = (const float*)d_in[17];
    const float* bp2    = (const float*)d_in[18];
    const float* Wn1    = (const float*)d_in[19];
    const float* bn1    = (const float*)d_in[20];
    const float* Wn2    = (const float*)d_in[21];
    const float* bn2    = (const float*)d_in[22];
    const float* Wv_mix = (const float*)d_in[23];
    const float* Wvel1  = (const float*)d_in[24];
    const float* bvel1  = (const float*)d_in[25];
    const float* Wvel2  = (const float*)d_in[26];

    float* out  = (float*)d_out;
    float* outH = out;
    float* outX = out + BB*NN*FF;
    float* outV = outX + BB*NN*3;

    cudaFuncSetAttribute(sake_kernel, cudaFuncAttributeMaxDynamicSharedMemorySize, SMEM_BYTES);

    wxt_kernel<<<CC, CC>>>(Wx);
    prenode_kernel<<<BB*NN, 128>>>(h, W_in, W_o1);
    sake_kernel<<<BB*NN, 256, SMEM_BYTES>>>(
        h, x, v, means, betas, b_in, W_o1, b_o1, W_o2, b_o2,
        Ws, bs, lgam, Wp1, bp1, Wp2, bp2,
        Wn1, bn1, Wn2, bn2, Wv_mix, Wvel1, bvel1, Wvel2,
        outH, outX, outV);
}

// round 12
// speedup vs baseline: 1.2774x; 1.2737x over previous
#include <cuda_runtime.h>
#include <cstdint>

#define BB 2
#define NN 256
#define FF 64
#define HH 64
#define KK 50
#define CC 256

// ---------------- device scratch ----------------
__device__ float g_A [BB*NN*KK];
__device__ float g_Bb[BB*NN*KK];
__device__ float g_U [BB*NN*HH];
__device__ float g_Wp[BB*NN*HH];

typedef unsigned long long ull;

// ---------------- helpers ----------------
__device__ __forceinline__ uint32_t smem_u32(const void* p) {
    uint32_t a;
    asm("{ .reg .u64 t; cvta.to.shared.u64 t, %1; cvt.u32.u64 %0, t; }" : "=r"(a) : "l"(p));
    return a;
}
__device__ __forceinline__ float siluf(float a) { return a * __fdividef(1.f, 1.f + __expf(-a)); }
__device__ __forceinline__ float sigm(float a)  { return __fdividef(1.f, 1.f + __expf(-a)); }
__device__ __forceinline__ float ftanh(float x) {
    float e = __expf(-2.f * fabsf(x));
    return copysignf(__fdividef(1.f - e, 1.f + e), x);
}
__device__ __forceinline__ void fma2(ull& acc, ull a, ull b) {
    asm("fma.rn.f32x2 %0, %1, %2, %0;" : "+l"(acc) : "l"(a), "l"(b));
}
__device__ __forceinline__ ull bcast2(float w) {
    ull r; asm("mov.b64 %0, {%1, %1};" : "=l"(r) : "f"(w)); return r;
}
__device__ __forceinline__ ull pack2(float a, float b) {
    ull r; asm("mov.b64 %0, {%1, %2};" : "=l"(r) : "f"(a), "f"(b)); return r;
}
__device__ __forceinline__ void unpack2(ull v, float& x, float& y) {
    asm("mov.b64 {%0, %1}, %2;" : "=f"(x), "=f"(y) : "l"(v));
}
__device__ __forceinline__ void cp16(uint32_t dst, const void* src) {
    asm volatile("cp.async.cg.shared.global [%0], [%1], 16;" :: "r"(dst), "l"(src) : "memory");
}
#define CP_COMMIT() asm volatile("cp.async.commit_group;" ::: "memory")
#define CP_WAIT0()  asm volatile("cp.async.wait_group 0;" ::: "memory")

// block reduce of 4 floats (8 warps / 256 threads). red >= 36 floats, 16B aligned.
template<int DO_MAX>
__device__ __forceinline__ float4 block_red4(float4 v, int tid, float* red) {
    #pragma unroll
    for (int o = 16; o > 0; o >>= 1) {
        float ax = __shfl_xor_sync(~0u, v.x, o), ay = __shfl_xor_sync(~0u, v.y, o);
        float az = __shfl_xor_sync(~0u, v.z, o), aw = __shfl_xor_sync(~0u, v.w, o);
        if (DO_MAX) { v.x = fmaxf(v.x, ax); v.y = fmaxf(v.y, ay); v.z = fmaxf(v.z, az); v.w = fmaxf(v.w, aw); }
        else        { v.x += ax; v.y += ay; v.z += az; v.w += aw; }
    }
    if ((tid & 31) == 0) ((float4*)red)[tid >> 5] = v;
    __syncthreads();
    if (tid < 32) {
        float4 r;
        if (tid < 8) r = ((float4*)red)[tid];
        else { float id = DO_MAX ? __int_as_float(0xff800000) : 0.f; r = make_float4(id, id, id, id); }
        #pragma unroll
        for (int o = 4; o > 0; o >>= 1) {
            float ax = __shfl_xor_sync(~0u, r.x, o), ay = __shfl_xor_sync(~0u, r.y, o);
            float az = __shfl_xor_sync(~0u, r.z, o), aw = __shfl_xor_sync(~0u, r.w, o);
            if (DO_MAX) { r.x = fmaxf(r.x, ax); r.y = fmaxf(r.y, ay); r.z = fmaxf(r.z, az); r.w = fmaxf(r.w, aw); }
            else        { r.x += ax; r.y += ay; r.z += az; r.w += aw; }
        }
        if (tid == 0) ((float4*)red)[8] = r;
    }
    __syncthreads();
    float4 out = ((float4*)red)[8];
    __syncthreads();
    return out;
}

// ---------------- K0: per-node precompute ----------------
__global__ void prenode_kernel(const float* __restrict__ h,
                               const float* __restrict__ W_in,
                               const float* __restrict__ W_o1) {
    __shared__ float hs[FF];
    int node = blockIdx.x, t = threadIdx.x;
    if (t < FF) hs[t] = h[node * FF + t];
    __syncthreads();
    if (t < KK) {
        float a = 0.f, bv = 0.f;
        #pragma unroll
        for (int f = 0; f < FF; f++) { float hv = hs[f]; a += hv * W_in[f*KK+t]; bv += hv * W_in[(FF+f)*KK+t]; }
        g_A[node*KK+t] = a; g_Bb[node*KK+t] = bv;
    } else if (t >= 64 && t < 128) {
        int c = t - 64;
        float u = 0.f, w = 0.f;
        #pragma unroll
        for (int f = 0; f < FF; f++) { float hv = hs[f]; u += hv * W_o1[f*HH+c]; w += hv * W_o1[(FF+f)*HH+c]; }
        g_U[node*HH+c] = u; g_Wp[node*HH+c] = w;
    }
}

// ---------------- smem layout (float offsets, compacted) ----------------
#define O_HE     0        // 256*65 = 16640
#define O_ATT    16640    // 1024
#define O_XDN    17664    // 1024
#define O_CMX    18688    // 256 (also phase-6 partial scratch)
#define O_CMY    18944
#define O_CMZ    19200
#define O_CN     19456
#define O_P1     19712
#define O_HCOMB  19776
#define O_N1     19840
#define O_HN     19904
#define O_HESUM  19968    // 256
#define O_HI     20224
#define O_WIB    20288
#define O_WON    20352
#define O_BO2    20416
#define O_BI     20480
#define O_MEAN   20544
#define O_BETA   20608
#define O_WS     20672    // 256
#define O_BSG    20928    // 8
#define O_XI     20936    // 4
#define O_RED    20940    // 36 (byte 83760, 16B aligned)
#define O_UNION  20992    // byte 83968, 16B aligned
// phase-1 view of union:
#define O_AS     20992    // 256*51 = 13056
#define O_WO1K   34048    // 3200
#define O_WO2    37248    // 4096 -> 41344
// phase-4 view of union:
#define O_HET    20992    // heT[256 c][76] = 19456 (4 groups of 16 j + 4-float holes)
#define O_WCH    40448    // 2 * 8192 = 16384 -> 56832 (byte 161792, 16B aligned)
// phase-6 view: cat[384] at O_HET
#define SMEM_FLOATS 56832
#define SMEM_BYTES  (SMEM_FLOATS*4)   // 227328

// ---------------- K1: fused per-(b,i) kernel ----------------
__global__ __launch_bounds__(256, 1)
void sake_kernel(const float* __restrict__ h, const float* __restrict__ x,
                 const float* __restrict__ v,
                 const float* __restrict__ means, const float* __restrict__ betas,
                 const float* __restrict__ b_in,
                 const float* __restrict__ W_o1, const float* __restrict__ b_o1,
                 const float* __restrict__ W_o2, const float* __restrict__ b_o2,
                 const float* __restrict__ Ws,  const float* __restrict__ bs,
                 const float* __restrict__ log_gamma,
                 const float* __restrict__ Wx,
                 const float* __restrict__ Wp1, const float* __restrict__ bp1,
                 const float* __restrict__ Wp2, const float* __restrict__ bp2,
                 const float* __restrict__ Wn1, const float* __restrict__ bn1,
                 const float* __restrict__ Wn2, const float* __restrict__ bn2,
                 const float* __restrict__ Wv_mix,
                 const float* __restrict__ Wvel1, const float* __restrict__ bvel1,
                 const float* __restrict__ Wvel2,
                 float* __restrict__ outH, float* __restrict__ outX,
                 float* __restrict__ outV) {
    extern __shared__ float sm[];
    const int tid = threadIdx.x, wid = tid >> 5, lane = tid & 31;
    const int bid = blockIdx.x, b = bid >> 8, i = bid & 255, nodeI = bid;

    float* he    = sm + O_HE;     // [256 j][65]
    float* att_s = sm + O_ATT;    // [256 j][4]
    float* xdn   = sm + O_XDN;    // [256 j][4]
    float* he_e  = sm + O_HESUM;
    float* hi_s  = sm + O_HI;
    float* wib   = sm + O_WIB;
    float* won   = sm + O_WON;
    float* bo2_s = sm + O_BO2;
    float* bi_s  = sm + O_BI;
    float* mn_s  = sm + O_MEAN;
    float* bt_s  = sm + O_BETA;
    float* ws_s  = sm + O_WS;
    float* bsg   = sm + O_BSG;
    float* xi_s  = sm + O_XI;
    float* red   = sm + O_RED;
    float* As    = sm + O_AS;
    float* wo1k  = sm + O_WO1K;
    float* wo2   = sm + O_WO2;
    float* heT   = sm + O_HET;    // [256 c][76]

    const uint32_t smb = smem_u32(sm);

    // ---- preload ----
    if (tid < FF) {
        hi_s[tid]  = h[nodeI*FF+tid];
        wib[tid]   = g_Wp[nodeI*HH+tid] + b_o1[tid];
        won[tid]   = W_o1[178*HH+tid];
        bo2_s[tid] = b_o2[tid];
    }
    if (tid < KK) {
        bi_s[tid] = g_Bb[nodeI*KK+tid] + b_in[tid];
        mn_s[tid] = means[tid];
        bt_s[tid] = betas[tid];
    }
    ws_s[tid] = Ws[tid];
    if (tid < 4) {
        bsg[tid]   = bs[tid];
        bsg[4+tid] = __expf(log_gamma[tid]);
        if (tid < 3) xi_s[tid] = x[nodeI*3+tid];
    }
    for (int idx = tid; idx < NN*KK; idx += 256) {
        int j2 = idx / KK, k = idx - j2*KK;
        As[j2*51+k] = g_A[b*NN*KK + idx];
    }
    for (int idx = tid; idx < NN*HH; idx += 256) {
        int j2 = idx >> 6, f = idx & 63;
        he[j2*65+f] = g_U[b*NN*HH + idx];
    }
    for (int idx = tid; idx < KK*HH; idx += 256) wo1k[idx] = W_o1[128*HH + idx];
    for (int idx = tid; idx < HH*HH; idx += 256) wo2[idx]  = W_o2[idx];
    __syncthreads();

    // ---- phase 1: edge model (thread = j), f32x2 ----
    const int j = tid;
    float xjx = x[(b*NN+j)*3+0], xjy = x[(b*NN+j)*3+1], xjz = x[(b*NN+j)*3+2];
    float dx = xjx - xi_s[0], dy = xjy - xi_s[1], dz = xjz - xi_s[2];
    float d2 = fmaxf(dx*dx + dy*dy + dz*dz, 0.f);
    float normv = sqrtf(d2 + 1e-5f);
    float rinv  = __fdividef(1.f, normv + 1e-5f);
    *(float4*)&xdn[j*4] = make_float4(dx*rinv, dy*rinv, dz*rinv, normv);
    float en = __expf(-normv);

    {
        float accf[64];
        #pragma unroll
        for (int f = 0; f < 64; f++) accf[f] = he[j*65+f] + wib[f] + normv*won[f];
        ull acc2[32];
        #pragma unroll
        for (int f2 = 0; f2 < 32; f2++) acc2[f2] = pack2(accf[2*f2], accf[2*f2+1]);

        #pragma unroll 2
        for (int k = 0; k < KK; k++) {
            float hk = As[j*51+k] + bi_s[k];
            float df = en - mn_s[k];
            float s  = __expf(-bt_s[k]*df*df) * hk;
            ull s2 = bcast2(s);
            const ulonglong2* wr = (const ulonglong2*)&wo1k[k*64];
            #pragma unroll
            for (int f4 = 0; f4 < 16; f4++) {
                ulonglong2 wv = wr[f4];
                fma2(acc2[2*f4],   wv.x, s2);
                fma2(acc2[2*f4+1], wv.y, s2);
            }
        }
        #pragma unroll
        for (int f2 = 0; f2 < 32; f2++) {
            float a0, a1; unpack2(acc2[f2], a0, a1);
            accf[2*f2] = siluf(a0); accf[2*f2+1] = siluf(a1);
        }

        #pragma unroll
        for (int g = 0; g < 4; g++) {
            ull o2[8];
            const ulonglong2* bo = (const ulonglong2*)&bo2_s[g*16];
            #pragma unroll
            for (int q = 0; q < 4; q++) { ulonglong2 bv = bo[q]; o2[2*q] = bv.x; o2[2*q+1] = bv.y; }
            #pragma unroll 8
            for (int f = 0; f < 64; f++) {
                ull ab = bcast2(accf[f]);
                const ulonglong2* wr = (const ulonglong2*)&wo2[f*64 + g*16];
                #pragma unroll
                for (int q = 0; q < 4; q++) {
                    ulonglong2 wv = wr[q];
                    fma2(o2[2*q],   wv.x, ab);
                    fma2(o2[2*q+1], wv.y, ab);
                }
            }
            #pragma unroll
            for (int q = 0; q < 8; q++) {
                float r0, r1; unpack2(o2[q], r0, r1);
                he[j*65 + g*16 + 2*q]     = r0;
                he[j*65 + g*16 + 2*q + 1] = r1;
            }
        }
    }

    // ---- phase 2: attentions (softmax over j) ----
    float z0 = bsg[0], z1 = bsg[1], z2 = bsg[2], z3 = bsg[3];
    for (int f = 0; f < 64; f++) {
        float a = he[j*65+f];
        z0 += a*ws_s[f*4+0]; z1 += a*ws_s[f*4+1]; z2 += a*ws_s[f*4+2]; z3 += a*ws_s[f*4+3];
    }
    z0 = (z0 > 0.f) ? z0 : 2.f*(__expf(0.5f*z0) - 1.f);
    z1 = (z1 > 0.f) ? z1 : 2.f*(__expf(0.5f*z1) - 1.f);
    z2 = (z2 > 0.f) ? z2 : 2.f*(__expf(0.5f*z2) - 1.f);
    z3 = (z3 > 0.f) ? z3 : 2.f*(__expf(0.5f*z3) - 1.f);
    float diag = (j == i) ? 1e5f : 0.f;
    float4 el = make_float4(-(normv+diag)*bsg[4], -(normv+diag)*bsg[5],
                            -(normv+diag)*bsg[6], -(normv+diag)*bsg[7]);
    float4 sl = make_float4(z0-diag, z1-diag, z2-diag, z3-diag);

    float4 m  = block_red4<1>(el, tid, red);
    float4 ee = make_float4(__expf(el.x-m.x), __expf(el.y-m.y), __expf(el.z-m.z), __expf(el.w-m.w));
    float4 s  = block_red4<0>(ee, tid, red);
    float4 eucl = make_float4(__fdividef(ee.x,s.x), __fdividef(ee.y,s.y),
                              __fdividef(ee.z,s.z), __fdividef(ee.w,s.w));
    m  = block_red4<1>(sl, tid, red);
    ee = make_float4(__expf(sl.x-m.x), __expf(sl.y-m.y), __expf(sl.z-m.z), __expf(sl.w-m.w));
    s  = block_red4<0>(ee, tid, red);
    float4 sem = make_float4(__fdividef(ee.x,s.x), __fdividef(ee.y,s.y),
                             __fdividef(ee.z,s.z), __fdividef(ee.w,s.w));
    float4 q4 = make_float4(eucl.x*sem.x, eucl.y*sem.y, eucl.z*sem.z, eucl.w*sem.w);
    m  = block_red4<1>(q4, tid, red);
    ee = make_float4(__expf(q4.x-m.x), __expf(q4.y-m.y), __expf(q4.z-m.z), __expf(q4.w-m.w));
    s  = block_red4<0>(ee, tid, red);
    att_s[j*4+0] = __fdividef(ee.x, s.x);
    att_s[j*4+1] = __fdividef(ee.y, s.y);
    att_s[j*4+2] = __fdividef(ee.z, s.z);
    att_s[j*4+3] = __fdividef(ee.w, s.w);
    __syncthreads();   // phase-1 union dead -> heT / Wx ring

    // ---- phase 4: coeff = tanh(he_att @ Wx), reduced over j (phase 3 folded in) ----
    // 8 warps = 8 n-slices of 32 n. lane = jp(0..3)*8 + nq(0..7).
    // Thread tile: 16 j (8 packed pairs) x 4 n. Pass = 64 j; 4 passes.
    // Ring: 2 x 32-c chunks (8 t-steps/pass -> half the barriers of R9).
    {
        const int jp = lane >> 3, nq = lane & 7;
        const int nb = wid*32 + nq*4;
        const int fme = tid >> 2, hme = tid & 3;
        float cmx[4] = {0,0,0,0}, cmy[4] = {0,0,0,0}, cmz[4] = {0,0,0,0};
        float heE = 0.f;

        #define STAGE(chunk, buf) do { \
            uint32_t _dst = smb + (uint32_t)(O_WCH + (buf)*8192)*4u + (uint32_t)tid*16u; \
            const float* _src = Wx + (chunk)*8192 + tid*4; \
            _Pragma("unroll") \
            for (int _r = 0; _r < 8; _r++) cp16(_dst + _r*4096u, _src + _r*1024); \
            CP_COMMIT(); \
        } while(0)

        for (int pass = 0; pass < 4; pass++) {
            const int j0 = pass*64;
            __syncthreads();            // prev pass ring + heT fully consumed
            STAGE(0, 0);
            // fill heT[c=tid][64 j of this pass] + accumulate he_e
            #pragma unroll 8
            for (int jj = 0; jj < 64; jj += 2) {
                int jn = j0 + jj;
                float v0 = he[jn*65 + fme]     * att_s[jn*4 + hme];
                float v1 = he[(jn+1)*65 + fme] * att_s[(jn+1)*4 + hme];
                heE += v0 + v1;
                int off = ((jj >> 4)*20) + (jj & 15);
                *(ull*)&heT[tid*76 + off] = pack2(v0, v1);
            }

            ull acc[4][8];
            #pragma unroll
            for (int n = 0; n < 4; n++)
                #pragma unroll
                for (int p = 0; p < 8; p++) acc[n][p] = 0ull;

            for (int t = 0; t < 8; t++) {
                CP_WAIT0();
                __syncthreads();        // buf t&1 + heT visible; compute(t-1) done
                if (t < 7) STAGE(t+1, (t+1)&1);

                const float* ar = heT + (t*32)*76 + jp*20;
                const float* wr = sm + O_WCH + (t&1)*8192 + nb;
                #pragma unroll 8
                for (int cc = 0; cc < 32; cc++) {
                    ulonglong2 a0 = *(const ulonglong2*)(ar);
                    ulonglong2 a1 = *(const ulonglong2*)(ar + 4);
                    ulonglong2 a2 = *(const ulonglong2*)(ar + 8);
                    ulonglong2 a3 = *(const ulonglong2*)(ar + 12);
                    float4 w4 = *(const float4*)(wr);
                    ull bb0 = bcast2(w4.x), bb1 = bcast2(w4.y);
                    ull bb2 = bcast2(w4.z), bb3 = bcast2(w4.w);
                    fma2(acc[0][0], a0.x, bb0); fma2(acc[0][1], a0.y, bb0);
                    fma2(acc[0][2], a1.x, bb0); fma2(acc[0][3], a1.y, bb0);
                    fma2(acc[0][4], a2.x, bb0); fma2(acc[0][5], a2.y, bb0);
                    fma2(acc[0][6], a3.x, bb0); fma2(acc[0][7], a3.y, bb0);
                    fma2(acc[1][0], a0.x, bb1); fma2(acc[1][1], a0.y, bb1);
                    fma2(acc[1][2], a1.x, bb1); fma2(acc[1][3], a1.y, bb1);
                    fma2(acc[1][4], a2.x, bb1); fma2(acc[1][5], a2.y, bb1);
                    fma2(acc[1][6], a3.x, bb1); fma2(acc[1][7], a3.y, bb1);
                    fma2(acc[2][0], a0.x, bb2); fma2(acc[2][1], a0.y, bb2);
                    fma2(acc[2][2], a1.x, bb2); fma2(acc[2][3], a1.y, bb2);
                    fma2(acc[2][4], a2.x, bb2); fma2(acc[2][5], a2.y, bb2);
                    fma2(acc[2][6], a3.x, bb2); fma2(acc[2][7], a3.y, bb2);
                    fma2(acc[3][0], a0.x, bb3); fma2(acc[3][1], a0.y, bb3);
                    fma2(acc[3][2], a1.x, bb3); fma2(acc[3][3], a1.y, bb3);
                    fma2(acc[3][4], a2.x, bb3); fma2(acc[3][5], a2.y, bb3);
                    fma2(acc[3][6], a3.x, bb3); fma2(acc[3][7], a3.y, bb3);
                    ar += 76; wr += 256;
                }
            }

            // epilogue: tanh + xd-weighted accumulate
            #pragma unroll
            for (int p = 0; p < 8; p++) {
                float4 x0 = *(const float4*)&xdn[(j0 + jp*16 + 2*p)*4];
                float4 x1 = *(const float4*)&xdn[(j0 + jp*16 + 2*p + 1)*4];
                #pragma unroll
                for (int n = 0; n < 4; n++) {
                    float c0, c1; unpack2(acc[n][p], c0, c1);
                    float t0 = ftanh(c0), t1 = ftanh(c1);
                    cmx[n] += x0.x*t0 + x1.x*t1;
                    cmy[n] += x0.y*t0 + x1.y*t1;
                    cmz[n] += x0.z*t0 + x1.z*t1;
                }
            }
        }
        he_e[tid] = heE;   // folded phase 3

        // reduce over jp groups (lane bits 3,4); lanes jp==0 store n-exclusive
        #pragma unroll
        for (int n = 0; n < 4; n++) {
            #pragma unroll
            for (int o = 8; o <= 16; o <<= 1) {
                cmx[n] += __shfl_xor_sync(~0u, cmx[n], o);
                cmy[n] += __shfl_xor_sync(~0u, cmy[n], o);
                cmz[n] += __shfl_xor_sync(~0u, cmz[n], o);
            }
        }
        if (jp == 0) {
            #pragma unroll
            for (int n = 0; n < 4; n++) {
                sm[O_CMX + nb + n] = cmx[n];
                sm[O_CMY + nb + n] = cmy[n];
                sm[O_CMZ + nb + n] = cmz[n];
            }
        }
    }
    __syncthreads();

    // ---- phase 5: comb_sum / comb_norm / delta_v ----
    float* cn    = sm + O_CN;
    float* p1_s  = sm + O_P1;
    float* hcomb = sm + O_HCOMB;
    float* n1_s  = sm + O_N1;
    float* hn_s  = sm + O_HN;
    float* part  = sm + O_CMX;    // reuse (cm dead after reads below)
    float* cat   = sm + O_HET;    // reuse (heT dead): [384]
    const float invN = 1.f/256.f;
    float csx = sm[O_CMX + tid]*invN, csy = sm[O_CMY + tid]*invN, csz = sm[O_CMZ + tid]*invN;
    cn[tid] = csx*csx + csy*csy + csz*csz;
    float wv = Wv_mix[tid];
    float4 dv4 = block_red4<0>(make_float4(wv*csx, wv*csy, wv*csz, 0.f), tid, red);
    cat[64 + tid] = he_e[tid];
    if (tid < 64) cat[tid] = hi_s[tid];

    // ---- phase 6: tail MLPs, 4-way split over 256 threads ----
    const int g6 = tid >> 6, o6 = tid & 63;
    {   // p1: 256 -> 64
        float a = 0.f;
        const float* wp = Wp1 + g6*64*64 + o6;
        const float* cnp = cn + g6*64;
        #pragma unroll 4
        for (int c = 0; c < 64; c++) a += cnp[c] * wp[c*64];
        part[tid] = a;
    }
    __syncthreads();
    if (tid < 64) {
        float a = bp1[tid] + part[tid] + part[64+tid] + part[128+tid] + part[192+tid];
        p1_s[tid] = siluf(a);
    }
    __syncthreads();
    {   // p2: 64 -> 64
        float a = 0.f;
        const float* wp = Wp2 + g6*16*64 + o6;
        #pragma unroll
        for (int f = 0; f < 16; f++) a += p1_s[g6*16+f] * wp[f*64];
        part[tid] = a;
    }
    __syncthreads();
    if (tid < 64) {
        float a = bp2[tid] + part[tid] + part[64+tid] + part[128+tid] + part[192+tid];
        float hc = siluf(a);
        hcomb[tid] = hc;
        cat[320 + tid] = hc;
    }
    __syncthreads();
    {   // n1: 384 -> 64
        float a = 0.f;
        const float* wp = Wn1 + g6*96*64 + o6;
        const float* cp = cat + g6*96;
        #pragma unroll 4
        for (int r = 0; r < 96; r++) a += cp[r] * wp[r*64];
        part[tid] = a;
    }
    __syncthreads();
    if (tid < 64) {
        float a = bn1[tid] + part[tid] + part[64+tid] + part[128+tid] + part[192+tid];
        n1_s[tid] = siluf(a);
    }
    __syncthreads();
    {   // n2: 64 -> 64
        float a = 0.f;
        const float* wp = Wn2 + g6*16*64 + o6;
        #pragma unroll
        for (int f = 0; f < 16; f++) a += n1_s[g6*16+f] * wp[f*64];
        part[tid] = a;
    }
    __syncthreads();
    if (tid < 64) {
        float a = bn2[tid] + part[tid] + part[64+tid] + part[128+tid] + part[192+tid];
        float hv = hi_s[tid] + siluf(a);
        hn_s[tid] = hv;
        outH[nodeI*64+tid] = hv;
    }
    __syncthreads();
    {   // vel1: 64 -> 64
        float a = 0.f;
        const float* wp = Wvel1 + g6*16*64 + o6;
        #pragma unroll
        for (int f = 0; f < 16; f++) a += hn_s[g6*16+f] * wp[f*64];
        part[tid] = a;
    }
    __syncthreads();
    float vl = 0.f;
    if (tid < 64) {
        float a = bvel1[tid] + part[tid] + part[64+tid] + part[128+tid] + part[192+tid];
        vl = siluf(a) * Wvel2[tid];
    }
    float4 vs = block_red4<0>(make_float4(vl, 0.f, 0.f, 0.f), tid, red);
    if (tid == 0) {
        float scale = 2.f * sigm(vs.x);
        float dvv[3] = {dv4.x, dv4.y, dv4.z};
        #pragma unroll
        for (int t = 0; t < 3; t++) {
            float vn = dvv[t] + scale * v[nodeI*3+t];
            outV[nodeI*3+t] = vn;
            outX[nodeI*3+t] = x[nodeI*3+t] + vn;
        }
    }
}

// ---------------- launch ----------------
extern "C" void kernel_launch(void* const* d_in, const int* in_sizes, int n_in,
                              void* d_out, int out_size) {
    const float* h      = (const float*)d_in[0];
    const float* x      = (const float*)d_in[1];
    const float* v      = (const float*)d_in[2];
    const float* means  = (const float*)d_in[3];
    const float* betas  = (const float*)d_in[4];
    const float* W_in   = (const float*)d_in[5];
    const float* b_in   = (const float*)d_in[6];
    const float* W_o1   = (const float*)d_in[7];
    const float* b_o1   = (const float*)d_in[8];
    const float* W_o2   = (const float*)d_in[9];
    const float* b_o2   = (const float*)d_in[10];
    const float* Ws     = (const float*)d_in[11];
    const float* bs     = (const float*)d_in[12];
    const float* lgam   = (const float*)d_in[13];
    const float* Wx     = (const float*)d_in[14];
    const float* Wp1    = (const float*)d_in[15];
    const float* bp1    = (const float*)d_in[16];
    const float* Wp2    = (const float*)d_in[17];
    const float* bp2    = (const float*)d_in[18];
    const float* Wn1    = (const float*)d_in[19];
    const float* bn1    = (const float*)d_in[20];
    const float* Wn2    = (const float*)d_in[21];
    const float* bn2    = (const float*)d_in[22];
    const float* Wv_mix = (const float*)d_in[23];
    const float* Wvel1  = (const float*)d_in[24];
    const float* bvel1  = (const float*)d_in[25];
    const float* Wvel2  = (const float*)d_in[26];

    float* out  = (float*)d_out;
    float* outH = out;
    float* outX = out + BB*NN*FF;
    float* outV = outX + BB*NN*3;

    cudaFuncSetAttribute(sake_kernel, cudaFuncAttributeMaxDynamicSharedMemorySize, SMEM_BYTES);

    prenode_kernel<<<BB*NN, 128>>>(h, W_in, W_o1);
    sake_kernel<<<BB*NN, 256, SMEM_BYTES>>>(
        h, x, v, means, betas, b_in, W_o1, b_o1, W_o2, b_o2,
        Ws, bs, lgam, Wx, Wp1, bp1, Wp2, bp2,
        Wn1, bn1, Wn2, bn2, Wv_mix, Wvel1, bvel1, Wvel2,
        outH, outX, outV);
}

// round 13
// speedup vs baseline: 1.2980x; 1.0162x over previous
#include <cuda_runtime.h>
#include <cstdint>

#define BB 2
#define NN 256
#define FF 64
#define HH 64
#define KK 50
#define CC 256

// ---------------- device scratch ----------------
__device__ float g_A [BB*NN*KK];
__device__ float g_Bb[BB*NN*KK];
__device__ float g_U [BB*NN*HH];
__device__ float g_Wp[BB*NN*HH];

typedef unsigned long long ull;

// ---------------- helpers ----------------
__device__ __forceinline__ uint32_t smem_u32(const void* p) {
    uint32_t a;
    asm("{ .reg .u64 t; cvta.to.shared.u64 t, %1; cvt.u32.u64 %0, t; }" : "=r"(a) : "l"(p));
    return a;
}
__device__ __forceinline__ float siluf(float a) { return a * __fdividef(1.f, 1.f + __expf(-a)); }
__device__ __forceinline__ float sigm(float a)  { return __fdividef(1.f, 1.f + __expf(-a)); }
__device__ __forceinline__ float ftanh(float x) {
    float e = __expf(-2.f * fabsf(x));
    return copysignf(__fdividef(1.f - e, 1.f + e), x);
}
__device__ __forceinline__ void fma2(ull& acc, ull a, ull b) {
    asm("fma.rn.f32x2 %0, %1, %2, %0;" : "+l"(acc) : "l"(a), "l"(b));
}
__device__ __forceinline__ ull bcast2(float w) {
    ull r; asm("mov.b64 %0, {%1, %1};" : "=l"(r) : "f"(w)); return r;
}
__device__ __forceinline__ ull pack2(float a, float b) {
    ull r; asm("mov.b64 %0, {%1, %2};" : "=l"(r) : "f"(a), "f"(b)); return r;
}
__device__ __forceinline__ void unpack2(ull v, float& x, float& y) {
    asm("mov.b64 {%0, %1}, %2;" : "=f"(x), "=f"(y) : "l"(v));
}
__device__ __forceinline__ void cp16(uint32_t dst, const void* src) {
    asm volatile("cp.async.cg.shared.global [%0], [%1], 16;" :: "r"(dst), "l"(src) : "memory");
}
#define CP_COMMIT() asm volatile("cp.async.commit_group;" ::: "memory")
#define CP_WAIT0()  asm volatile("cp.async.wait_group 0;" ::: "memory")

// block reduce of 4 floats (8 warps / 256 threads). red >= 36 floats, 16B aligned.
template<int DO_MAX>
__device__ __forceinline__ float4 block_red4(float4 v, int tid, float* red) {
    #pragma unroll
    for (int o = 16; o > 0; o >>= 1) {
        float ax = __shfl_xor_sync(~0u, v.x, o), ay = __shfl_xor_sync(~0u, v.y, o);
        float az = __shfl_xor_sync(~0u, v.z, o), aw = __shfl_xor_sync(~0u, v.w, o);
        if (DO_MAX) { v.x = fmaxf(v.x, ax); v.y = fmaxf(v.y, ay); v.z = fmaxf(v.z, az); v.w = fmaxf(v.w, aw); }
        else        { v.x += ax; v.y += ay; v.z += az; v.w += aw; }
    }
    if ((tid & 31) == 0) ((float4*)red)[tid >> 5] = v;
    __syncthreads();
    if (tid < 32) {
        float4 r;
        if (tid < 8) r = ((float4*)red)[tid];
        else { float id = DO_MAX ? __int_as_float(0xff800000) : 0.f; r = make_float4(id, id, id, id); }
        #pragma unroll
        for (int o = 4; o > 0; o >>= 1) {
            float ax = __shfl_xor_sync(~0u, r.x, o), ay = __shfl_xor_sync(~0u, r.y, o);
            float az = __shfl_xor_sync(~0u, r.z, o), aw = __shfl_xor_sync(~0u, r.w, o);
            if (DO_MAX) { r.x = fmaxf(r.x, ax); r.y = fmaxf(r.y, ay); r.z = fmaxf(r.z, az); r.w = fmaxf(r.w, aw); }
            else        { r.x += ax; r.y += ay; r.z += az; r.w += aw; }
        }
        if (tid == 0) ((float4*)red)[8] = r;
    }
    __syncthreads();
    float4 out = ((float4*)red)[8];
    __syncthreads();
    return out;
}

// ---------------- K0: per-node precompute ----------------
__global__ void prenode_kernel(const float* __restrict__ h,
                               const float* __restrict__ W_in,
                               const float* __restrict__ W_o1) {
    __shared__ float hs[FF];
    int node = blockIdx.x, t = threadIdx.x;
    if (t < FF) hs[t] = h[node * FF + t];
    __syncthreads();
    if (t < KK) {
        float a = 0.f, bv = 0.f;
        #pragma unroll
        for (int f = 0; f < FF; f++) { float hv = hs[f]; a += hv * W_in[f*KK+t]; bv += hv * W_in[(FF+f)*KK+t]; }
        g_A[node*KK+t] = a; g_Bb[node*KK+t] = bv;
    } else if (t >= 64 && t < 128) {
        int c = t - 64;
        float u = 0.f, w = 0.f;
        #pragma unroll
        for (int f = 0; f < FF; f++) { float hv = hs[f]; u += hv * W_o1[f*HH+c]; w += hv * W_o1[(FF+f)*HH+c]; }
        g_U[node*HH+c] = u; g_Wp[node*HH+c] = w;
    }
}

// ---------------- smem layout (float offsets, compacted) ----------------
#define O_HE     0        // 256*65 = 16640
#define O_ATT    16640    // 1024
#define O_XDN    17664    // 1024
#define O_CMX    18688    // 256 (also phase-6 partial scratch)
#define O_CMY    18944
#define O_CMZ    19200
#define O_CN     19456
#define O_P1     19712
#define O_HCOMB  19776
#define O_N1     19840
#define O_HN     19904
#define O_HESUM  19968    // 256
#define O_HI     20224
#define O_WIB    20288
#define O_WON    20352
#define O_BO2    20416
#define O_BI     20480
#define O_MEAN   20544
#define O_BETA   20608
#define O_WS     20672    // 256
#define O_BSG    20928    // 8
#define O_XI     20936    // 4
#define O_RED    20940    // 36 (byte 83760, 16B aligned)
#define O_UNION  20992    // byte 83968, 16B aligned
// phase-1 view of union:
#define O_AS     20992    // 256*51 = 13056
#define O_WO1K   34048    // 3200
#define O_WO2    37248    // 4096 -> 41344
// phase-4 view of union:
#define O_HET    20992    // heT[256 c][76] = 19456 (4 groups of 16 j + 4-float holes)
#define O_WCH    40448    // 2 * 8192 = 16384 -> 56832 (byte 161792, 16B aligned)
// phase-6 view: cat[384] at O_HET
#define SMEM_FLOATS 56832
#define SMEM_BYTES  (SMEM_FLOATS*4)   // 227328

// ---------------- K1: fused per-(b,i) kernel ----------------
__global__ __launch_bounds__(256, 1)
void sake_kernel(const float* __restrict__ h, const float* __restrict__ x,
                 const float* __restrict__ v,
                 const float* __restrict__ means, const float* __restrict__ betas,
                 const float* __restrict__ b_in,
                 const float* __restrict__ W_o1, const float* __restrict__ b_o1,
                 const float* __restrict__ W_o2, const float* __restrict__ b_o2,
                 const float* __restrict__ Ws,  const float* __restrict__ bs,
                 const float* __restrict__ log_gamma,
                 const float* __restrict__ Wx,
                 const float* __restrict__ Wp1, const float* __restrict__ bp1,
                 const float* __restrict__ Wp2, const float* __restrict__ bp2,
                 const float* __restrict__ Wn1, const float* __restrict__ bn1,
                 const float* __restrict__ Wn2, const float* __restrict__ bn2,
                 const float* __restrict__ Wv_mix,
                 const float* __restrict__ Wvel1, const float* __restrict__ bvel1,
                 const float* __restrict__ Wvel2,
                 float* __restrict__ outH, float* __restrict__ outX,
                 float* __restrict__ outV) {
    extern __shared__ float sm[];
    const int tid = threadIdx.x, wid = tid >> 5, lane = tid & 31;
    const int bid = blockIdx.x, b = bid >> 8, i = bid & 255, nodeI = bid;

    float* he    = sm + O_HE;     // [256 j][65]
    float* att_s = sm + O_ATT;    // [256 j][4]
    float* xdn   = sm + O_XDN;    // [256 j][4]
    float* he_e  = sm + O_HESUM;
    float* hi_s  = sm + O_HI;
    float* wib   = sm + O_WIB;
    float* won   = sm + O_WON;
    float* bo2_s = sm + O_BO2;
    float* bi_s  = sm + O_BI;
    float* mn_s  = sm + O_MEAN;
    float* bt_s  = sm + O_BETA;
    float* ws_s  = sm + O_WS;
    float* bsg   = sm + O_BSG;
    float* xi_s  = sm + O_XI;
    float* red   = sm + O_RED;
    float* As    = sm + O_AS;
    float* wo1k  = sm + O_WO1K;
    float* wo2   = sm + O_WO2;
    float* heT   = sm + O_HET;    // [256 c][76]

    const uint32_t smb = smem_u32(sm);

    // ---- preload ----
    if (tid < FF) {
        hi_s[tid]  = h[nodeI*FF+tid];
        wib[tid]   = g_Wp[nodeI*HH+tid] + b_o1[tid];
        won[tid]   = W_o1[178*HH+tid];
        bo2_s[tid] = b_o2[tid];
    }
    if (tid < KK) {
        bi_s[tid] = g_Bb[nodeI*KK+tid] + b_in[tid];
        mn_s[tid] = means[tid];
        bt_s[tid] = betas[tid];
    }
    ws_s[tid] = Ws[tid];
    if (tid < 4) {
        bsg[tid]   = bs[tid];
        bsg[4+tid] = __expf(log_gamma[tid]);
        if (tid < 3) xi_s[tid] = x[nodeI*3+tid];
    }
    for (int idx = tid; idx < NN*KK; idx += 256) {
        int j2 = idx / KK, k = idx - j2*KK;
        As[j2*51+k] = g_A[b*NN*KK + idx];
    }
    for (int idx = tid; idx < NN*HH; idx += 256) {
        int j2 = idx >> 6, f = idx & 63;
        he[j2*65+f] = g_U[b*NN*HH + idx];
    }
    for (int idx = tid; idx < KK*HH; idx += 256) wo1k[idx] = W_o1[128*HH + idx];
    for (int idx = tid; idx < HH*HH; idx += 256) wo2[idx]  = W_o2[idx];
    __syncthreads();

    // ---- phase 1: edge model (thread = j), f32x2 ----
    const int j = tid;
    float xjx = x[(b*NN+j)*3+0], xjy = x[(b*NN+j)*3+1], xjz = x[(b*NN+j)*3+2];
    float dx = xjx - xi_s[0], dy = xjy - xi_s[1], dz = xjz - xi_s[2];
    float d2 = fmaxf(dx*dx + dy*dy + dz*dz, 0.f);
    float normv = sqrtf(d2 + 1e-5f);
    float rinv  = __fdividef(1.f, normv + 1e-5f);
    *(float4*)&xdn[j*4] = make_float4(dx*rinv, dy*rinv, dz*rinv, normv);
    float en = __expf(-normv);

    {
        float accf[64];
        #pragma unroll
        for (int f = 0; f < 64; f++) accf[f] = he[j*65+f] + wib[f] + normv*won[f];
        ull acc2[32];
        #pragma unroll
        for (int f2 = 0; f2 < 32; f2++) acc2[f2] = pack2(accf[2*f2], accf[2*f2+1]);

        #pragma unroll 2
        for (int k = 0; k < KK; k++) {
            float hk = As[j*51+k] + bi_s[k];
            float df = en - mn_s[k];
            float s  = __expf(-bt_s[k]*df*df) * hk;
            ull s2 = bcast2(s);
            const ulonglong2* wr = (const ulonglong2*)&wo1k[k*64];
            #pragma unroll
            for (int f4 = 0; f4 < 16; f4++) {
                ulonglong2 wv = wr[f4];
                fma2(acc2[2*f4],   wv.x, s2);
                fma2(acc2[2*f4+1], wv.y, s2);
            }
        }
        #pragma unroll
        for (int f2 = 0; f2 < 32; f2++) {
            float a0, a1; unpack2(acc2[f2], a0, a1);
            accf[2*f2] = siluf(a0); accf[2*f2+1] = siluf(a1);
        }

        #pragma unroll
        for (int g = 0; g < 4; g++) {
            ull o2[8];
            const ulonglong2* bo = (const ulonglong2*)&bo2_s[g*16];
            #pragma unroll
            for (int q = 0; q < 4; q++) { ulonglong2 bv = bo[q]; o2[2*q] = bv.x; o2[2*q+1] = bv.y; }
            #pragma unroll 8
            for (int f = 0; f < 64; f++) {
                ull ab = bcast2(accf[f]);
                const ulonglong2* wr = (const ulonglong2*)&wo2[f*64 + g*16];
                #pragma unroll
                for (int q = 0; q < 4; q++) {
                    ulonglong2 wv = wr[q];
                    fma2(o2[2*q],   wv.x, ab);
                    fma2(o2[2*q+1], wv.y, ab);
                }
            }
            #pragma unroll
            for (int q = 0; q < 8; q++) {
                float r0, r1; unpack2(o2[q], r0, r1);
                he[j*65 + g*16 + 2*q]     = r0;
                he[j*65 + g*16 + 2*q + 1] = r1;
            }
        }
    }

    // ---- phase 2: attentions (softmax over j), f32x2 z-loop ----
    float z0, z1, z2, z3;
    {
        ull z01 = pack2(bsg[0], bsg[1]);
        ull z23 = pack2(bsg[2], bsg[3]);
        #pragma unroll 8
        for (int f = 0; f < 64; f++) {
            ull ab = bcast2(he[j*65+f]);
            ulonglong2 wv = *(const ulonglong2*)&ws_s[f*4];
            fma2(z01, wv.x, ab);
            fma2(z23, wv.y, ab);
        }
        unpack2(z01, z0, z1);
        unpack2(z23, z2, z3);
    }
    z0 = (z0 > 0.f) ? z0 : 2.f*(__expf(0.5f*z0) - 1.f);
    z1 = (z1 > 0.f) ? z1 : 2.f*(__expf(0.5f*z1) - 1.f);
    z2 = (z2 > 0.f) ? z2 : 2.f*(__expf(0.5f*z2) - 1.f);
    z3 = (z3 > 0.f) ? z3 : 2.f*(__expf(0.5f*z3) - 1.f);
    float diag = (j == i) ? 1e5f : 0.f;
    float4 el = make_float4(-(normv+diag)*bsg[4], -(normv+diag)*bsg[5],
                            -(normv+diag)*bsg[6], -(normv+diag)*bsg[7]);
    float4 sl = make_float4(z0-diag, z1-diag, z2-diag, z3-diag);

    float4 m  = block_red4<1>(el, tid, red);
    float4 ee = make_float4(__expf(el.x-m.x), __expf(el.y-m.y), __expf(el.z-m.z), __expf(el.w-m.w));
    float4 s  = block_red4<0>(ee, tid, red);
    float4 eucl = make_float4(__fdividef(ee.x,s.x), __fdividef(ee.y,s.y),
                              __fdividef(ee.z,s.z), __fdividef(ee.w,s.w));
    m  = block_red4<1>(sl, tid, red);
    ee = make_float4(__expf(sl.x-m.x), __expf(sl.y-m.y), __expf(sl.z-m.z), __expf(sl.w-m.w));
    s  = block_red4<0>(ee, tid, red);
    float4 sem = make_float4(__fdividef(ee.x,s.x), __fdividef(ee.y,s.y),
                             __fdividef(ee.z,s.z), __fdividef(ee.w,s.w));
    float4 q4 = make_float4(eucl.x*sem.x, eucl.y*sem.y, eucl.z*sem.z, eucl.w*sem.w);
    m  = block_red4<1>(q4, tid, red);
    ee = make_float4(__expf(q4.x-m.x), __expf(q4.y-m.y), __expf(q4.z-m.z), __expf(q4.w-m.w));
    s  = block_red4<0>(ee, tid, red);
    att_s[j*4+0] = __fdividef(ee.x, s.x);
    att_s[j*4+1] = __fdividef(ee.y, s.y);
    att_s[j*4+2] = __fdividef(ee.z, s.z);
    att_s[j*4+3] = __fdividef(ee.w, s.w);
    __syncthreads();   // phase-1 union dead -> heT / Wx ring

    // ---- phase 4: coeff = tanh(he_att @ Wx), reduced over j (phase 3 folded in) ----
    // 8 warps = 8 n-slices of 32 n. lane = jp(0..3)*8 + nq(0..7).
    // Thread tile: 16 j (8 packed pairs) x 4 n. Pass = 64 j; 4 passes.
    // Ring: 2 x 32-c chunks, ROTATED chunk order per pass so the last two chunks
    // of pass p are resident as the first two of pass p+1 (no wait, no restage).
    {
        const int jp = lane >> 3, nq = lane & 7;
        const int nb = wid*32 + nq*4;
        const int fme = tid >> 2, hme = tid & 3;
        float cmx[4] = {0,0,0,0}, cmy[4] = {0,0,0,0}, cmz[4] = {0,0,0,0};
        float heE = 0.f;

        #define STAGE(chunk, buf) do { \
            uint32_t _dst = smb + (uint32_t)(O_WCH + (buf)*8192)*4u + (uint32_t)tid*16u; \
            const float* _src = Wx + (chunk)*8192 + tid*4; \
            _Pragma("unroll") \
            for (int _r = 0; _r < 8; _r++) cp16(_dst + _r*4096u, _src + _r*1024); \
            CP_COMMIT(); \
        } while(0)

        for (int pass = 0; pass < 4; pass++) {
            const int j0 = pass*64;
            const int sgn = (8 - 2*pass) & 7;   // chunk rotation start: 0,6,4,2
            __syncthreads();            // prev pass ring + heT fully consumed
            if (pass == 0) STAGE(0, 0);
            // fill heT[c=tid][64 j of this pass] + accumulate he_e
            #pragma unroll 8
            for (int jj = 0; jj < 64; jj += 2) {
                int jn = j0 + jj;
                float v0 = he[jn*65 + fme]     * att_s[jn*4 + hme];
                float v1 = he[(jn+1)*65 + fme] * att_s[(jn+1)*4 + hme];
                heE += v0 + v1;
                int off = ((jj >> 4)*20) + (jj & 15);
                *(ull*)&heT[tid*76 + off] = pack2(v0, v1);
            }

            ull acc[4][8];
            #pragma unroll
            for (int n = 0; n < 4; n++)
                #pragma unroll
                for (int p = 0; p < 8; p++) acc[n][p] = 0ull;

            for (int t = 0; t < 8; t++) {
                const int ck = (sgn + t) & 7;   // chunk consumed this step (buf = t&1)
                if (pass == 0 || t >= 2) CP_WAIT0();
                __syncthreads();        // buf t&1 + heT visible; compute(t-1) done
                if (t < 7 && (pass == 0 || t >= 1)) STAGE((sgn + t + 1) & 7, (t+1)&1);

                const float* ar = heT + (ck*32)*76 + jp*20;
                const float* wr = sm + O_WCH + (t&1)*8192 + nb;
                #pragma unroll 8
                for (int cc = 0; cc < 32; cc++) {
                    ulonglong2 a0 = *(const ulonglong2*)(ar);
                    ulonglong2 a1 = *(const ulonglong2*)(ar + 4);
                    ulonglong2 a2 = *(const ulonglong2*)(ar + 8);
                    ulonglong2 a3 = *(const ulonglong2*)(ar + 12);
                    float4 w4 = *(const float4*)(wr);
                    ull bb0 = bcast2(w4.x), bb1 = bcast2(w4.y);
                    ull bb2 = bcast2(w4.z), bb3 = bcast2(w4.w);
                    fma2(acc[0][0], a0.x, bb0); fma2(acc[0][1], a0.y, bb0);
                    fma2(acc[0][2], a1.x, bb0); fma2(acc[0][3], a1.y, bb0);
                    fma2(acc[0][4], a2.x, bb0); fma2(acc[0][5], a2.y, bb0);
                    fma2(acc[0][6], a3.x, bb0); fma2(acc[0][7], a3.y, bb0);
                    fma2(acc[1][0], a0.x, bb1); fma2(acc[1][1], a0.y, bb1);
                    fma2(acc[1][2], a1.x, bb1); fma2(acc[1][3], a1.y, bb1);
                    fma2(acc[1][4], a2.x, bb1); fma2(acc[1][5], a2.y, bb1);
                    fma2(acc[1][6], a3.x, bb1); fma2(acc[1][7], a3.y, bb1);
                    fma2(acc[2][0], a0.x, bb2); fma2(acc[2][1], a0.y, bb2);
                    fma2(acc[2][2], a1.x, bb2); fma2(acc[2][3], a1.y, bb2);
                    fma2(acc[2][4], a2.x, bb2); fma2(acc[2][5], a2.y, bb2);
                    fma2(acc[2][6], a3.x, bb2); fma2(acc[2][7], a3.y, bb2);
                    fma2(acc[3][0], a0.x, bb3); fma2(acc[3][1], a0.y, bb3);
                    fma2(acc[3][2], a1.x, bb3); fma2(acc[3][3], a1.y, bb3);
                    fma2(acc[3][4], a2.x, bb3); fma2(acc[3][5], a2.y, bb3);
                    fma2(acc[3][6], a3.x, bb3); fma2(acc[3][7], a3.y, bb3);
                    ar += 76; wr += 256;
                }
            }

            // epilogue: tanh + xd-weighted accumulate
            #pragma unroll
            for (int p = 0; p < 8; p++) {
                float4 x0 = *(const float4*)&xdn[(j0 + jp*16 + 2*p)*4];
                float4 x1 = *(const float4*)&xdn[(j0 + jp*16 + 2*p + 1)*4];
                #pragma unroll
                for (int n = 0; n < 4; n++) {
                    float c0, c1; unpack2(acc[n][p], c0, c1);
                    float t0 = ftanh(c0), t1 = ftanh(c1);
                    cmx[n] += x0.x*t0 + x1.x*t1;
                    cmy[n] += x0.y*t0 + x1.y*t1;
                    cmz[n] += x0.z*t0 + x1.z*t1;
                }
            }
        }
        he_e[tid] = heE;   // folded phase 3

        // reduce over jp groups (lane bits 3,4); lanes jp==0 store n-exclusive
        #pragma unroll
        for (int n = 0; n < 4; n++) {
            #pragma unroll
            for (int o = 8; o <= 16; o <<= 1) {
                cmx[n] += __shfl_xor_sync(~0u, cmx[n], o);
                cmy[n] += __shfl_xor_sync(~0u, cmy[n], o);
                cmz[n] += __shfl_xor_sync(~0u, cmz[n], o);
            }
        }
        if (jp == 0) {
            #pragma unroll
            for (int n = 0; n < 4; n++) {
                sm[O_CMX + nb + n] = cmx[n];
                sm[O_CMY + nb + n] = cmy[n];
                sm[O_CMZ + nb + n] = cmz[n];
            }
        }
    }
    __syncthreads();

    // ---- phase 5: comb_sum / comb_norm / delta_v ----
    float* cn    = sm + O_CN;
    float* p1_s  = sm + O_P1;
    float* hcomb = sm + O_HCOMB;
    float* n1_s  = sm + O_N1;
    float* hn_s  = sm + O_HN;
    float* part  = sm + O_CMX;    // reuse (cm dead after reads below)
    float* cat   = sm + O_HET;    // reuse (heT dead): [384]
    const float invN = 1.f/256.f;
    float csx = sm[O_CMX + tid]*invN, csy = sm[O_CMY + tid]*invN, csz = sm[O_CMZ + tid]*invN;
    cn[tid] = csx*csx + csy*csy + csz*csz;
    float wv = Wv_mix[tid];
    float4 dv4 = block_red4<0>(make_float4(wv*csx, wv*csy, wv*csz, 0.f), tid, red);
    cat[64 + tid] = he_e[tid];
    if (tid < 64) cat[tid] = hi_s[tid];

    // ---- phase 6: tail MLPs, 4-way split over 256 threads ----
    const int g6 = tid >> 6, o6 = tid & 63;
    {   // p1: 256 -> 64
        float a = 0.f;
        const float* wp = Wp1 + g6*64*64 + o6;
        const float* cnp = cn + g6*64;
        #pragma unroll 4
        for (int c = 0; c < 64; c++) a += cnp[c] * wp[c*64];
        part[tid] = a;
    }
    __syncthreads();
    if (tid < 64) {
        float a = bp1[tid] + part[tid] + part[64+tid] + part[128+tid] + part[192+tid];
        p1_s[tid] = siluf(a);
    }
    __syncthreads();
    {   // p2: 64 -> 64
        float a = 0.f;
        const float* wp = Wp2 + g6*16*64 + o6;
        #pragma unroll
        for (int f = 0; f < 16; f++) a += p1_s[g6*16+f] * wp[f*64];
        part[tid] = a;
    }
    __syncthreads();
    if (tid < 64) {
        float a = bp2[tid] + part[tid] + part[64+tid] + part[128+tid] + part[192+tid];
        float hc = siluf(a);
        hcomb[tid] = hc;
        cat[320 + tid] = hc;
    }
    __syncthreads();
    {   // n1: 384 -> 64
        float a = 0.f;
        const float* wp = Wn1 + g6*96*64 + o6;
        const float* cp = cat + g6*96;
        #pragma unroll 4
        for (int r = 0; r < 96; r++) a += cp[r] * wp[r*64];
        part[tid] = a;
    }
    __syncthreads();
    if (tid < 64) {
        float a = bn1[tid] + part[tid] + part[64+tid] + part[128+tid] + part[192+tid];
        n1_s[tid] = siluf(a);
    }
    __syncthreads();
    {   // n2: 64 -> 64
        float a = 0.f;
        const float* wp = Wn2 + g6*16*64 + o6;
        #pragma unroll
        for (int f = 0; f < 16; f++) a += n1_s[g6*16+f] * wp[f*64];
        part[tid] = a;
    }
    __syncthreads();
    if (tid < 64) {
        float a = bn2[tid] + part[tid] + part[64+tid] + part[128+tid] + part[192+tid];
        float hv = hi_s[tid] + siluf(a);
        hn_s[tid] = hv;
        outH[nodeI*64+tid] = hv;
    }
    __syncthreads();
    {   // vel1: 64 -> 64
        float a = 0.f;
        const float* wp = Wvel1 + g6*16*64 + o6;
        #pragma unroll
        for (int f = 0; f < 16; f++) a += hn_s[g6*16+f] * wp[f*64];
        part[tid] = a;
    }
    __syncthreads();
    float vl = 0.f;
    if (tid < 64) {
        float a = bvel1[tid] + part[tid] + part[64+tid] + part[128+tid] + part[192+tid];
        vl = siluf(a) * Wvel2[tid];
    }
    float4 vs = block_red4<0>(make_float4(vl, 0.f, 0.f, 0.f), tid, red);
    if (tid == 0) {
        float scale = 2.f * sigm(vs.x);
        float dvv[3] = {dv4.x, dv4.y, dv4.z};
        #pragma unroll
        for (int t = 0; t < 3; t++) {
            float vn = dvv[t] + scale * v[nodeI*3+t];
            outV[nodeI*3+t] = vn;
            outX[nodeI*3+t] = x[nodeI*3+t] + vn;
        }
    }
}

// ---------------- launch ----------------
extern "C" void kernel_launch(void* const* d_in, const int* in_sizes, int n_in,
                              void* d_out, int out_size) {
    const float* h      = (const float*)d_in[0];
    const float* x      = (const float*)d_in[1];
    const float* v      = (const float*)d_in[2];
    const float* means  = (const float*)d_in[3];
    const float* betas  = (const float*)d_in[4];
    const float* W_in   = (const float*)d_in[5];
    const float* b_in   = (const float*)d_in[6];
    const float* W_o1   = (const float*)d_in[7];
    const float* b_o1   = (const float*)d_in[8];
    const float* W_o2   = (const float*)d_in[9];
    const float* b_o2   = (const float*)d_in[10];
    const float* Ws     = (const float*)d_in[11];
    const float* bs     = (const float*)d_in[12];
    const float* lgam   = (const float*)d_in[13];
    const float* Wx     = (const float*)d_in[14];
    const float* Wp1    = (const float*)d_in[15];
    const float* bp1    = (const float*)d_in[16];
    const float* Wp2    = (const float*)d_in[17];
    const float* bp2    = (const float*)d_in[18];
    const float* Wn1    = (const float*)d_in[19];
    const float* bn1    = (const float*)d_in[20];
    const float* Wn2    = (const float*)d_in[21];
    const float* bn2    = (const float*)d_in[22];
    const float* Wv_mix = (const float*)d_in[23];
    const float* Wvel1  = (const float*)d_in[24];
    const float* bvel1  = (const float*)d_in[25];
    const float* Wvel2  = (const float*)d_in[26];

    float* out  = (float*)d_out;
    float* outH = out;
    float* outX = out + BB*NN*FF;
    float* outV = outX + BB*NN*3;

    cudaFuncSetAttribute(sake_kernel, cudaFuncAttributeMaxDynamicSharedMemorySize, SMEM_BYTES);

    prenode_kernel<<<BB*NN, 128>>>(h, W_in, W_o1);
    sake_kernel<<<BB*NN, 256, SMEM_BYTES>>>(
        h, x, v, means, betas, b_in, W_o1, b_o1, W_o2, b_o2,
        Ws, bs, lgam, Wx, Wp1, bp1, Wp2, bp2,
        Wn1, bn1, Wn2, bn2, Wv_mix, Wvel1, bvel1, Wvel2,
        outH, outX, outV);
}

// round 14
// speedup vs baseline: 1.4114x; 1.0874x over previous
#include <cuda_runtime.h>
#include <cstdint>

#define BB 2
#define NN 256
#define FF 64
#define HH 64
#define KK 50
#define CC 256

// ---------------- device scratch ----------------
__device__ float g_A [BB*NN*KK];
__device__ float g_Bb[BB*NN*KK];
__device__ float g_U [BB*NN*HH];
__device__ float g_Wp[BB*NN*HH];
__device__ float g_he  [BB*NN*NN*FF];     // [512 node][256 j][64 f] = 32MB
__device__ float g_attG[BB*NN*NN*4];      // [512][256][4]
__device__ float g_xdnG[BB*NN*NN*4];      // [512][256][4]
__device__ float g_cmp [BB*NN*2*3*CC];    // [512][jh][xyz][256]
__device__ float g_heE [BB*NN*2*CC];      // [512][jh][256]

typedef unsigned long long ull;

// ---------------- helpers ----------------
__device__ __forceinline__ uint32_t smem_u32(const void* p) {
    uint32_t a;
    asm("{ .reg .u64 t; cvta.to.shared.u64 t, %1; cvt.u32.u64 %0, t; }" : "=r"(a) : "l"(p));
    return a;
}
__device__ __forceinline__ float siluf(float a) { return a * __fdividef(1.f, 1.f + __expf(-a)); }
__device__ __forceinline__ float sigm(float a)  { return __fdividef(1.f, 1.f + __expf(-a)); }
__device__ __forceinline__ float ftanh(float x) {
    float e = __expf(-2.f * fabsf(x));
    return copysignf(__fdividef(1.f - e, 1.f + e), x);
}
__device__ __forceinline__ void fma2(ull& acc, ull a, ull b) {
    asm("fma.rn.f32x2 %0, %1, %2, %0;" : "+l"(acc) : "l"(a), "l"(b));
}
__device__ __forceinline__ ull bcast2(float w) {
    ull r; asm("mov.b64 %0, {%1, %1};" : "=l"(r) : "f"(w)); return r;
}
__device__ __forceinline__ ull pack2(float a, float b) {
    ull r; asm("mov.b64 %0, {%1, %2};" : "=l"(r) : "f"(a), "f"(b)); return r;
}
__device__ __forceinline__ void unpack2(ull v, float& x, float& y) {
    asm("mov.b64 {%0, %1}, %2;" : "=f"(x), "=f"(y) : "l"(v));
}
__device__ __forceinline__ void cp16(uint32_t dst, const void* src) {
    asm volatile("cp.async.cg.shared.global [%0], [%1], 16;" :: "r"(dst), "l"(src) : "memory");
}
#define CP_COMMIT() asm volatile("cp.async.commit_group;" ::: "memory")
#define CP_WAIT0()  asm volatile("cp.async.wait_group 0;" ::: "memory")

// block reduce of 4 floats (8 warps / 256 threads). red >= 36 floats, 16B aligned.
template<int DO_MAX>
__device__ __forceinline__ float4 block_red4(float4 v, int tid, float* red) {
    #pragma unroll
    for (int o = 16; o > 0; o >>= 1) {
        float ax = __shfl_xor_sync(~0u, v.x, o), ay = __shfl_xor_sync(~0u, v.y, o);
        float az = __shfl_xor_sync(~0u, v.z, o), aw = __shfl_xor_sync(~0u, v.w, o);
        if (DO_MAX) { v.x = fmaxf(v.x, ax); v.y = fmaxf(v.y, ay); v.z = fmaxf(v.z, az); v.w = fmaxf(v.w, aw); }
        else        { v.x += ax; v.y += ay; v.z += az; v.w += aw; }
    }
    if ((tid & 31) == 0) ((float4*)red)[tid >> 5] = v;
    __syncthreads();
    if (tid < 32) {
        float4 r;
        if (tid < 8) r = ((float4*)red)[tid];
        else { float id = DO_MAX ? __int_as_float(0xff800000) : 0.f; r = make_float4(id, id, id, id); }
        #pragma unroll
        for (int o = 4; o > 0; o >>= 1) {
            float ax = __shfl_xor_sync(~0u, r.x, o), ay = __shfl_xor_sync(~0u, r.y, o);
            float az = __shfl_xor_sync(~0u, r.z, o), aw = __shfl_xor_sync(~0u, r.w, o);
            if (DO_MAX) { r.x = fmaxf(r.x, ax); r.y = fmaxf(r.y, ay); r.z = fmaxf(r.z, az); r.w = fmaxf(r.w, aw); }
            else        { r.x += ax; r.y += ay; r.z += az; r.w += aw; }
        }
        if (tid == 0) ((float4*)red)[8] = r;
    }
    __syncthreads();
    float4 out = ((float4*)red)[8];
    __syncthreads();
    return out;
}

// ---------------- K0: per-node precompute ----------------
__global__ void prenode_kernel(const float* __restrict__ h,
                               const float* __restrict__ W_in,
                               const float* __restrict__ W_o1) {
    __shared__ float hs[FF];
    int node = blockIdx.x, t = threadIdx.x;
    if (t < FF) hs[t] = h[node * FF + t];
    __syncthreads();
    if (t < KK) {
        float a = 0.f, bv = 0.f;
        #pragma unroll
        for (int f = 0; f < FF; f++) { float hv = hs[f]; a += hv * W_in[f*KK+t]; bv += hv * W_in[(FF+f)*KK+t]; }
        g_A[node*KK+t] = a; g_Bb[node*KK+t] = bv;
    } else if (t >= 64 && t < 128) {
        int c = t - 64;
        float u = 0.f, w = 0.f;
        #pragma unroll
        for (int f = 0; f < FF; f++) { float hv = hs[f]; u += hv * W_o1[f*HH+c]; w += hv * W_o1[(FF+f)*HH+c]; }
        g_U[node*HH+c] = u; g_Wp[node*HH+c] = w;
    }
}

// ================= K1: phases 0-2 per node =================
#define K1_HE    0        // 16640
#define K1_ATT   16640    // 1024
#define K1_XDN   17664    // 1024
#define K1_WIB   18688
#define K1_WON   18752
#define K1_BO2   18816
#define K1_BI    18880
#define K1_MEAN  18944
#define K1_BETA  19008
#define K1_WS    19072    // 256
#define K1_BSG   19328    // 8
#define K1_XI    19336    // 4
#define K1_RED   19340    // 36
#define K1_AS    19392    // 13056
#define K1_WO1K  32448    // 3200
#define K1_WO2   35648    // 4096 -> 39744
#define K1_FLOATS 39744
#define K1_BYTES  (K1_FLOATS*4)   // 158976

__global__ __launch_bounds__(256, 1)
void sake_k1(const float* __restrict__ x,
             const float* __restrict__ means, const float* __restrict__ betas,
             const float* __restrict__ b_in,
             const float* __restrict__ W_o1, const float* __restrict__ b_o1,
             const float* __restrict__ b_o2,
             const float* __restrict__ W_o2,
             const float* __restrict__ Ws,  const float* __restrict__ bs,
             const float* __restrict__ log_gamma) {
    extern __shared__ float sm[];
    const int tid = threadIdx.x;
    const int bid = blockIdx.x, b = bid >> 8, i = bid & 255, nodeI = bid;

    float* he    = sm + K1_HE;
    float* att_s = sm + K1_ATT;
    float* xdn   = sm + K1_XDN;
    float* wib   = sm + K1_WIB;
    float* won   = sm + K1_WON;
    float* bo2_s = sm + K1_BO2;
    float* bi_s  = sm + K1_BI;
    float* mn_s  = sm + K1_MEAN;
    float* bt_s  = sm + K1_BETA;
    float* ws_s  = sm + K1_WS;
    float* bsg   = sm + K1_BSG;
    float* xi_s  = sm + K1_XI;
    float* red   = sm + K1_RED;
    float* As    = sm + K1_AS;
    float* wo1k  = sm + K1_WO1K;
    float* wo2   = sm + K1_WO2;

    if (tid < FF) {
        wib[tid]   = g_Wp[nodeI*HH+tid] + b_o1[tid];
        won[tid]   = W_o1[178*HH+tid];
        bo2_s[tid] = b_o2[tid];
    }
    if (tid < KK) {
        bi_s[tid] = g_Bb[nodeI*KK+tid] + b_in[tid];
        mn_s[tid] = means[tid];
        bt_s[tid] = betas[tid];
    }
    ws_s[tid] = Ws[tid];
    if (tid < 4) {
        bsg[tid]   = bs[tid];
        bsg[4+tid] = __expf(log_gamma[tid]);
        if (tid < 3) xi_s[tid] = x[nodeI*3+tid];
    }
    for (int idx = tid; idx < NN*KK; idx += 256) {
        int j2 = idx / KK, k = idx - j2*KK;
        As[j2*51+k] = g_A[b*NN*KK + idx];
    }
    for (int idx = tid; idx < NN*HH; idx += 256) {
        int j2 = idx >> 6, f = idx & 63;
        he[j2*65+f] = g_U[b*NN*HH + idx];
    }
    for (int idx = tid; idx < KK*HH; idx += 256) wo1k[idx] = W_o1[128*HH + idx];
    for (int idx = tid; idx < HH*HH; idx += 256) wo2[idx]  = W_o2[idx];
    __syncthreads();

    // phase 0/1
    const int j = tid;
    float xjx = x[(b*NN+j)*3+0], xjy = x[(b*NN+j)*3+1], xjz = x[(b*NN+j)*3+2];
    float dx = xjx - xi_s[0], dy = xjy - xi_s[1], dz = xjz - xi_s[2];
    float d2 = fmaxf(dx*dx + dy*dy + dz*dz, 0.f);
    float normv = sqrtf(d2 + 1e-5f);
    float rinv  = __fdividef(1.f, normv + 1e-5f);
    *(float4*)&xdn[j*4] = make_float4(dx*rinv, dy*rinv, dz*rinv, normv);
    float en = __expf(-normv);

    {
        float accf[64];
        #pragma unroll
        for (int f = 0; f < 64; f++) accf[f] = he[j*65+f] + wib[f] + normv*won[f];
        ull acc2[32];
        #pragma unroll
        for (int f2 = 0; f2 < 32; f2++) acc2[f2] = pack2(accf[2*f2], accf[2*f2+1]);

        #pragma unroll 2
        for (int k = 0; k < KK; k++) {
            float hk = As[j*51+k] + bi_s[k];
            float df = en - mn_s[k];
            float s  = __expf(-bt_s[k]*df*df) * hk;
            ull s2 = bcast2(s);
            const ulonglong2* wr = (const ulonglong2*)&wo1k[k*64];
            #pragma unroll
            for (int f4 = 0; f4 < 16; f4++) {
                ulonglong2 wv = wr[f4];
                fma2(acc2[2*f4],   wv.x, s2);
                fma2(acc2[2*f4+1], wv.y, s2);
            }
        }
        #pragma unroll
        for (int f2 = 0; f2 < 32; f2++) {
            float a0, a1; unpack2(acc2[f2], a0, a1);
            accf[2*f2] = siluf(a0); accf[2*f2+1] = siluf(a1);
        }

        #pragma unroll
        for (int g = 0; g < 4; g++) {
            ull o2[8];
            const ulonglong2* bo = (const ulonglong2*)&bo2_s[g*16];
            #pragma unroll
            for (int q = 0; q < 4; q++) { ulonglong2 bv = bo[q]; o2[2*q] = bv.x; o2[2*q+1] = bv.y; }
            #pragma unroll 8
            for (int f = 0; f < 64; f++) {
                ull ab = bcast2(accf[f]);
                const ulonglong2* wr = (const ulonglong2*)&wo2[f*64 + g*16];
                #pragma unroll
                for (int q = 0; q < 4; q++) {
                    ulonglong2 wv = wr[q];
                    fma2(o2[2*q],   wv.x, ab);
                    fma2(o2[2*q+1], wv.y, ab);
                }
            }
            #pragma unroll
            for (int q = 0; q < 8; q++) {
                float r0, r1; unpack2(o2[q], r0, r1);
                he[j*65 + g*16 + 2*q]     = r0;
                he[j*65 + g*16 + 2*q + 1] = r1;
            }
        }
    }

    // phase 2
    float z0, z1, z2, z3;
    {
        ull z01 = pack2(bsg[0], bsg[1]);
        ull z23 = pack2(bsg[2], bsg[3]);
        #pragma unroll 8
        for (int f = 0; f < 64; f++) {
            ull ab = bcast2(he[j*65+f]);
            ulonglong2 wv = *(const ulonglong2*)&ws_s[f*4];
            fma2(z01, wv.x, ab);
            fma2(z23, wv.y, ab);
        }
        unpack2(z01, z0, z1);
        unpack2(z23, z2, z3);
    }
    z0 = (z0 > 0.f) ? z0 : 2.f*(__expf(0.5f*z0) - 1.f);
    z1 = (z1 > 0.f) ? z1 : 2.f*(__expf(0.5f*z1) - 1.f);
    z2 = (z2 > 0.f) ? z2 : 2.f*(__expf(0.5f*z2) - 1.f);
    z3 = (z3 > 0.f) ? z3 : 2.f*(__expf(0.5f*z3) - 1.f);
    float diag = (j == i) ? 1e5f : 0.f;
    float4 el = make_float4(-(normv+diag)*bsg[4], -(normv+diag)*bsg[5],
                            -(normv+diag)*bsg[6], -(normv+diag)*bsg[7]);
    float4 sl = make_float4(z0-diag, z1-diag, z2-diag, z3-diag);

    float4 m  = block_red4<1>(el, tid, red);
    float4 ee = make_float4(__expf(el.x-m.x), __expf(el.y-m.y), __expf(el.z-m.z), __expf(el.w-m.w));
    float4 s  = block_red4<0>(ee, tid, red);
    float4 eucl = make_float4(__fdividef(ee.x,s.x), __fdividef(ee.y,s.y),
                              __fdividef(ee.z,s.z), __fdividef(ee.w,s.w));
    m  = block_red4<1>(sl, tid, red);
    ee = make_float4(__expf(sl.x-m.x), __expf(sl.y-m.y), __expf(sl.z-m.z), __expf(sl.w-m.w));
    s  = block_red4<0>(ee, tid, red);
    float4 sem = make_float4(__fdividef(ee.x,s.x), __fdividef(ee.y,s.y),
                             __fdividef(ee.z,s.z), __fdividef(ee.w,s.w));
    float4 q4 = make_float4(eucl.x*sem.x, eucl.y*sem.y, eucl.z*sem.z, eucl.w*sem.w);
    m  = block_red4<1>(q4, tid, red);
    ee = make_float4(__expf(q4.x-m.x), __expf(q4.y-m.y), __expf(q4.z-m.z), __expf(q4.w-m.w));
    s  = block_red4<0>(ee, tid, red);
    att_s[j*4+0] = __fdividef(ee.x, s.x);
    att_s[j*4+1] = __fdividef(ee.y, s.y);
    att_s[j*4+2] = __fdividef(ee.z, s.z);
    att_s[j*4+3] = __fdividef(ee.w, s.w);
    __syncthreads();

    // dump he/att/xdn to global (coalesced)
    for (int idx = tid; idx < NN*FF; idx += 256)
        g_he[nodeI*(NN*FF) + idx] = he[(idx >> 6)*65 + (idx & 63)];
    for (int idx = tid; idx < NN*4; idx += 256) {
        g_attG[nodeI*(NN*4) + idx] = att_s[idx];
        g_xdnG[nodeI*(NN*4) + idx] = xdn[idx];
    }
}

// ================= K2: phase 4, (node, j-half) blocks =================
#define K2_HEH   0        // 128*65 = 8320
#define K2_ATT   8320     // 512
#define K2_XDN   8832     // 512
#define K2_HET   9344     // heT[256 c][76] = 19456 -> 28800 (byte 37376, 16B ok)
#define K2_WCH   28800    // 2*8192 = 16384 -> 45184 (byte 115200, 16B ok)
#define K2_FLOATS 45184
#define K2_BYTES  (K2_FLOATS*4)   // 180736

__global__ __launch_bounds__(256, 1)
void sake_k2(const float* __restrict__ Wx) {
    extern __shared__ float sm[];
    const int tid = threadIdx.x, wid = tid >> 5, lane = tid & 31;
    const int bid = blockIdx.x;
    const int node = bid >> 1, jh = bid & 1;

    float* heH  = sm + K2_HEH;   // [128 j][65]
    float* attH = sm + K2_ATT;   // [128 j][4]
    float* xdnH = sm + K2_XDN;   // [128 j][4]
    float* heT  = sm + K2_HET;   // [256 c][76]
    const uint32_t smb = smem_u32(sm);

    for (int idx = tid; idx < 128*FF; idx += 256)
        heH[(idx >> 6)*65 + (idx & 63)] = g_he[node*(NN*FF) + jh*(128*FF) + idx];
    for (int idx = tid; idx < 512; idx += 256) {
        attH[idx] = g_attG[node*(NN*4) + jh*512 + idx];
        xdnH[idx] = g_xdnG[node*(NN*4) + jh*512 + idx];
    }
    __syncthreads();

    const int jp = lane >> 3, nq = lane & 7;
    const int nb = wid*32 + nq*4;
    const int fme = tid >> 2, hme = tid & 3;
    float cmx[4] = {0,0,0,0}, cmy[4] = {0,0,0,0}, cmz[4] = {0,0,0,0};
    float heE = 0.f;

    #define STAGE(chunk, buf) do { \
        uint32_t _dst = smb + (uint32_t)(K2_WCH + (buf)*8192)*4u + (uint32_t)tid*16u; \
        const float* _src = Wx + (chunk)*8192 + tid*4; \
        _Pragma("unroll") \
        for (int _r = 0; _r < 8; _r++) cp16(_dst + _r*4096u, _src + _r*1024); \
        CP_COMMIT(); \
    } while(0)

    for (int pass = 0; pass < 2; pass++) {
        const int j0 = pass*64;                  // local j base within half
        const int sgn = (8 - 2*pass) & 7;        // 0, 6
        __syncthreads();
        if (pass == 0) STAGE(0, 0);
        #pragma unroll 8
        for (int jj = 0; jj < 64; jj += 2) {
            int jn = j0 + jj;
            float v0 = heH[jn*65 + fme]     * attH[jn*4 + hme];
            float v1 = heH[(jn+1)*65 + fme] * attH[(jn+1)*4 + hme];
            heE += v0 + v1;
            int off = ((jj >> 4)*20) + (jj & 15);
            *(ull*)&heT[tid*76 + off] = pack2(v0, v1);
        }

        ull acc[4][8];
        #pragma unroll
        for (int n = 0; n < 4; n++)
            #pragma unroll
            for (int p = 0; p < 8; p++) acc[n][p] = 0ull;

        for (int t = 0; t < 8; t++) {
            const int ck = (sgn + t) & 7;
            if (pass == 0 || t >= 2) CP_WAIT0();
            __syncthreads();
            if (t < 7 && (pass == 0 || t >= 1)) STAGE((sgn + t + 1) & 7, (t+1)&1);

            const float* ar = heT + (ck*32)*76 + jp*20;
            const float* wr = sm + K2_WCH + (t&1)*8192 + nb;
            #pragma unroll 8
            for (int cc = 0; cc < 32; cc++) {
                ulonglong2 a0 = *(const ulonglong2*)(ar);
                ulonglong2 a1 = *(const ulonglong2*)(ar + 4);
                ulonglong2 a2 = *(const ulonglong2*)(ar + 8);
                ulonglong2 a3 = *(const ulonglong2*)(ar + 12);
                float4 w4 = *(const float4*)(wr);
                ull bb0 = bcast2(w4.x), bb1 = bcast2(w4.y);
                ull bb2 = bcast2(w4.z), bb3 = bcast2(w4.w);
                fma2(acc[0][0], a0.x, bb0); fma2(acc[0][1], a0.y, bb0);
                fma2(acc[0][2], a1.x, bb0); fma2(acc[0][3], a1.y, bb0);
                fma2(acc[0][4], a2.x, bb0); fma2(acc[0][5], a2.y, bb0);
                fma2(acc[0][6], a3.x, bb0); fma2(acc[0][7], a3.y, bb0);
                fma2(acc[1][0], a0.x, bb1); fma2(acc[1][1], a0.y, bb1);
                fma2(acc[1][2], a1.x, bb1); fma2(acc[1][3], a1.y, bb1);
                fma2(acc[1][4], a2.x, bb1); fma2(acc[1][5], a2.y, bb1);
                fma2(acc[1][6], a3.x, bb1); fma2(acc[1][7], a3.y, bb1);
                fma2(acc[2][0], a0.x, bb2); fma2(acc[2][1], a0.y, bb2);
                fma2(acc[2][2], a1.x, bb2); fma2(acc[2][3], a1.y, bb2);
                fma2(acc[2][4], a2.x, bb2); fma2(acc[2][5], a2.y, bb2);
                fma2(acc[2][6], a3.x, bb2); fma2(acc[2][7], a3.y, bb2);
                fma2(acc[3][0], a0.x, bb3); fma2(acc[3][1], a0.y, bb3);
                fma2(acc[3][2], a1.x, bb3); fma2(acc[3][3], a1.y, bb3);
                fma2(acc[3][4], a2.x, bb3); fma2(acc[3][5], a2.y, bb3);
                fma2(acc[3][6], a3.x, bb3); fma2(acc[3][7], a3.y, bb3);
                ar += 76; wr += 256;
            }
        }

        #pragma unroll
        for (int p = 0; p < 8; p++) {
            float4 x0 = *(const float4*)&xdnH[(j0 + jp*16 + 2*p)*4];
            float4 x1 = *(const float4*)&xdnH[(j0 + jp*16 + 2*p + 1)*4];
            #pragma unroll
            for (int n = 0; n < 4; n++) {
                float c0, c1; unpack2(acc[n][p], c0, c1);
                float t0 = ftanh(c0), t1 = ftanh(c1);
                cmx[n] += x0.x*t0 + x1.x*t1;
                cmy[n] += x0.y*t0 + x1.y*t1;
                cmz[n] += x0.z*t0 + x1.z*t1;
            }
        }
    }
    g_heE[node*512 + jh*256 + tid] = heE;

    #pragma unroll
    for (int n = 0; n < 4; n++) {
        #pragma unroll
        for (int o = 8; o <= 16; o <<= 1) {
            cmx[n] += __shfl_xor_sync(~0u, cmx[n], o);
            cmy[n] += __shfl_xor_sync(~0u, cmy[n], o);
            cmz[n] += __shfl_xor_sync(~0u, cmz[n], o);
        }
    }
    if (jp == 0) {
        const int base = node*1536 + jh*768;
        #pragma unroll
        for (int n = 0; n < 4; n++) {
            g_cmp[base +       nb + n] = cmx[n];
            g_cmp[base + 256 + nb + n] = cmy[n];
            g_cmp[base + 512 + nb + n] = cmz[n];
        }
    }
}

// ================= K3: phases 5-6 per node =================
__global__ __launch_bounds__(256, 1)
void sake_k3(const float* __restrict__ h, const float* __restrict__ x,
             const float* __restrict__ v,
             const float* __restrict__ Wv_mix,
             const float* __restrict__ Wp1, const float* __restrict__ bp1,
             const float* __restrict__ Wp2, const float* __restrict__ bp2,
             const float* __restrict__ Wn1, const float* __restrict__ bn1,
             const float* __restrict__ Wn2, const float* __restrict__ bn2,
             const float* __restrict__ Wvel1, const float* __restrict__ bvel1,
             const float* __restrict__ Wvel2,
             float* __restrict__ outH, float* __restrict__ outX,
             float* __restrict__ outV) {
    __shared__ __align__(16) float red[40];
    __shared__ float cn[256], part[256], cat[384];
    __shared__ float p1_s[64], hcomb[64], n1_s[64], hn_s[64], hi_s[64];
    const int tid = threadIdx.x;
    const int node = blockIdx.x;

    const float invN = 1.f/256.f;
    const int base = node*1536;
    float csx = (g_cmp[base + tid]       + g_cmp[base + 768 + tid])  * invN;
    float csy = (g_cmp[base + 256 + tid] + g_cmp[base + 1024 + tid]) * invN;
    float csz = (g_cmp[base + 512 + tid] + g_cmp[base + 1280 + tid]) * invN;
    cn[tid] = csx*csx + csy*csy + csz*csz;
    float wv = Wv_mix[tid];
    cat[64 + tid] = g_heE[node*512 + tid] + g_heE[node*512 + 256 + tid];
    if (tid < 64) { float hv = h[node*64 + tid]; cat[tid] = hv; hi_s[tid] = hv; }
    float4 dv4 = block_red4<0>(make_float4(wv*csx, wv*csy, wv*csz, 0.f), tid, red);

    const int g6 = tid >> 6, o6 = tid & 63;
    {   // p1: 256 -> 64
        float a = 0.f;
        const float* wp = Wp1 + g6*64*64 + o6;
        const float* cnp = cn + g6*64;
        #pragma unroll 4
        for (int c = 0; c < 64; c++) a += cnp[c] * wp[c*64];
        part[tid] = a;
    }
    __syncthreads();
    if (tid < 64) {
        float a = bp1[tid] + part[tid] + part[64+tid] + part[128+tid] + part[192+tid];
        p1_s[tid] = siluf(a);
    }
    __syncthreads();
    {   // p2: 64 -> 64
        float a = 0.f;
        const float* wp = Wp2 + g6*16*64 + o6;
        #pragma unroll
        for (int f = 0; f < 16; f++) a += p1_s[g6*16+f] * wp[f*64];
        part[tid] = a;
    }
    __syncthreads();
    if (tid < 64) {
        float a = bp2[tid] + part[tid] + part[64+tid] + part[128+tid] + part[192+tid];
        float hc = siluf(a);
        hcomb[tid] = hc;
        cat[320 + tid] = hc;
    }
    __syncthreads();
    {   // n1: 384 -> 64
        float a = 0.f;
        const float* wp = Wn1 + g6*96*64 + o6;
        const float* cp = cat + g6*96;
        #pragma unroll 4
        for (int r = 0; r < 96; r++) a += cp[r] * wp[r*64];
        part[tid] = a;
    }
    __syncthreads();
    if (tid < 64) {
        float a = bn1[tid] + part[tid] + part[64+tid] + part[128+tid] + part[192+tid];
        n1_s[tid] = siluf(a);
    }
    __syncthreads();
    {   // n2: 64 -> 64
        float a = 0.f;
        const float* wp = Wn2 + g6*16*64 + o6;
        #pragma unroll
        for (int f = 0; f < 16; f++) a += n1_s[g6*16+f] * wp[f*64];
        part[tid] = a;
    }
    __syncthreads();
    if (tid < 64) {
        float a = bn2[tid] + part[tid] + part[64+tid] + part[128+tid] + part[192+tid];
        float hv = hi_s[tid] + siluf(a);
        hn_s[tid] = hv;
        outH[node*64+tid] = hv;
    }
    __syncthreads();
    {   // vel1: 64 -> 64
        float a = 0.f;
        const float* wp = Wvel1 + g6*16*64 + o6;
        #pragma unroll
        for (int f = 0; f < 16; f++) a += hn_s[g6*16+f] * wp[f*64];
        part[tid] = a;
    }
    __syncthreads();
    float vl = 0.f;
    if (tid < 64) {
        float a = bvel1[tid] + part[tid] + part[64+tid] + part[128+tid] + part[192+tid];
        vl = siluf(a) * Wvel2[tid];
    }
    float4 vs = block_red4<0>(make_float4(vl, 0.f, 0.f, 0.f), tid, red);
    if (tid == 0) {
        float scale = 2.f * sigm(vs.x);
        float dvv[3] = {dv4.x, dv4.y, dv4.z};
        #pragma unroll
        for (int t = 0; t < 3; t++) {
            float vn = dvv[t] + scale * v[node*3+t];
            outV[node*3+t] = vn;
            outX[node*3+t] = x[node*3+t] + vn;
        }
    }
}

// ---------------- launch ----------------
extern "C" void kernel_launch(void* const* d_in, const int* in_sizes, int n_in,
                              void* d_out, int out_size) {
    const float* h      = (const float*)d_in[0];
    const float* x      = (const float*)d_in[1];
    const float* v      = (const float*)d_in[2];
    const float* means  = (const float*)d_in[3];
    const float* betas  = (const float*)d_in[4];
    const float* W_in   = (const float*)d_in[5];
    const float* b_in   = (const float*)d_in[6];
    const float* W_o1   = (const float*)d_in[7];
    const float* b_o1   = (const float*)d_in[8];
    const float* W_o2   = (const float*)d_in[9];
    const float* b_o2   = (const float*)d_in[10];
    const float* Ws     = (const float*)d_in[11];
    const float* bs     = (const float*)d_in[12];
    const float* lgam   = (const float*)d_in[13];
    const float* Wx     = (const float*)d_in[14];
    const float* Wp1    = (const float*)d_in[15];
    const float* bp1    = (const float*)d_in[16];
    const float* Wp2    = (const float*)d_in[17];
    const float* bp2    = (const float*)d_in[18];
    const float* Wn1    = (const float*)d_in[19];
    const float* bn1    = (const float*)d_in[20];
    const float* Wn2    = (const float*)d_in[21];
    const float* bn2    = (const float*)d_in[22];
    const float* Wv_mix = (const float*)d_in[23];
    const float* Wvel1  = (const float*)d_in[24];
    const float* bvel1  = (const float*)d_in[25];
    const float* Wvel2  = (const float*)d_in[26];

    float* out  = (float*)d_out;
    float* outH = out;
    float* outX = out + BB*NN*FF;
    float* outV = outX + BB*NN*3;

    cudaFuncSetAttribute(sake_k1, cudaFuncAttributeMaxDynamicSharedMemorySize, K1_BYTES);
    cudaFuncSetAttribute(sake_k2, cudaFuncAttributeMaxDynamicSharedMemorySize, K2_BYTES);

    prenode_kernel<<<BB*NN, 128>>>(h, W_in, W_o1);
    sake_k1<<<BB*NN, 256, K1_BYTES>>>(x, means, betas, b_in, W_o1, b_o1, b_o2, W_o2,
                                      Ws, bs, lgam);
    sake_k2<<<BB*NN*2, 256, K2_BYTES>>>(Wx);
    sake_k3<<<BB*NN, 256>>>(h, x, v, Wv_mix, Wp1, bp1, Wp2, bp2,
                            Wn1, bn1, Wn2, bn2, Wvel1, bvel1, Wvel2,
                            outH, outX, outV);
}